// round 2
// baseline (speedup 1.0000x reference)
#include <cuda_runtime.h>
#include <cstdint>
#include <cstddef>

// Problem constants
#define NB   16
#define LSEQ 9216
#define NTOK 147456          // NB*LSEQ
#define CDIM 192
#define DI   384             // d_inner
#define NXZ  768             // 2*DI
#define DTR  12              // dt_rank
#define NPROJ 14             // dt_rank + 2*d_state
#define NC   36              // scan chunks per sequence
#define CL   256             // chunk length (NC*CL = LSEQ)

// -------- scratch (device globals; no allocation allowed) --------
__device__ float g_xn[(size_t)NTOK * CDIM];   // layernorm output
__device__ float g_xz[(size_t)NTOK * NXZ];    // cols [0,384)=xb, [384,768)=z
__device__ float g_u [(size_t)NTOK * DI];     // silu(conv(xb))
__device__ float g_dt[(size_t)NTOK * DI];     // softplus(dt)
__device__ float g_yp[(size_t)NTOK * DI];     // gated scan output (pre out-proj)
__device__ float g_Bv[NTOK];
__device__ float g_Cv[NTOK];
__device__ float g_ca[NB * NC * DI];          // chunk A-product
__device__ float g_ch[NB * NC * DI];          // chunk end-state (from h=0)
__device__ float g_hi[NB * NC * DI];          // chunk initial state

__device__ __forceinline__ float sigmoidf_(float v) { return 1.0f / (1.0f + expf(-v)); }
__device__ __forceinline__ float siluf_(float v)    { return v * sigmoidf_(v); }
__device__ __forceinline__ float softplusf_(float v){ return v > 20.0f ? v : log1pf(expf(v)); }

// ---------------- LayerNorm: one warp per token (192 = 6*32) ----------------
__global__ void ln_kernel(const float* __restrict__ x,
                          const float* __restrict__ w,
                          const float* __restrict__ b)
{
    int warp = threadIdx.x >> 5, lane = threadIdx.x & 31;
    size_t t = (size_t)blockIdx.x * 8 + warp;
    const float* row = x + t * CDIM;
    float v[6];
    float s = 0.f;
#pragma unroll
    for (int r = 0; r < 6; r++) { v[r] = row[lane + 32*r]; s += v[r]; }
#pragma unroll
    for (int o = 16; o; o >>= 1) s += __shfl_xor_sync(0xffffffffu, s, o);
    float mu = s * (1.0f/192.0f);
    float q = 0.f;
#pragma unroll
    for (int r = 0; r < 6; r++) { float d = v[r] - mu; q += d*d; }
#pragma unroll
    for (int o = 16; o; o >>= 1) q += __shfl_xor_sync(0xffffffffu, q, o);
    float inv = rsqrtf(q * (1.0f/192.0f) + 1e-5f);
    float* out = g_xn + t * CDIM;
#pragma unroll
    for (int r = 0; r < 6; r++) {
        int c = lane + 32*r;
        out[c] = (v[r] - mu) * inv * w[c] + b[c];
    }
}

// ---------------- Generic fp32 GEMM: C[M,N] = A[M,K] @ B[K,N] (+ add) ----------------
// BM=128, BN=64, BK=16, 256 threads, 8x4 per thread. All dims divide exactly.
__global__ __launch_bounds__(256)
void gemm_kernel(const float* __restrict__ A, const float* __restrict__ B,
                 const float* __restrict__ addsrc, float* __restrict__ C,
                 int M, int N, int K)
{
    __shared__ float As[16][128];
    __shared__ float Bs[16][64];
    int tid = threadIdx.x;
    int bm = blockIdx.y * 128;
    int bn = blockIdx.x * 64;
    int ty = tid >> 4, tx = tid & 15;
    int row0 = ty * 8, col0 = tx * 4;
    float acc[8][4];
#pragma unroll
    for (int i = 0; i < 8; i++)
#pragma unroll
        for (int j = 0; j < 4; j++) acc[i][j] = 0.f;

    int arow = tid >> 2;            // 0..63
    int acol = (tid & 3) * 4;       // 0,4,8,12
    int brow = tid >> 4;            // 0..15
    int bcol = (tid & 15) * 4;      // 0..60

    for (int k0 = 0; k0 < K; k0 += 16) {
#pragma unroll
        for (int half = 0; half < 2; half++) {
            int r = arow + half * 64;
            float4 v = *(const float4*)(A + (size_t)(bm + r) * K + k0 + acol);
            As[acol+0][r] = v.x; As[acol+1][r] = v.y;
            As[acol+2][r] = v.z; As[acol+3][r] = v.w;
        }
        {
            float4 v = *(const float4*)(B + (size_t)(k0 + brow) * N + bn + bcol);
            *(float4*)&Bs[brow][bcol] = v;
        }
        __syncthreads();
#pragma unroll
        for (int k = 0; k < 16; k++) {
            float4 a0 = *(const float4*)&As[k][row0];
            float4 a1 = *(const float4*)&As[k][row0 + 4];
            float4 b0 = *(const float4*)&Bs[k][col0];
            float a[8] = {a0.x,a0.y,a0.z,a0.w,a1.x,a1.y,a1.z,a1.w};
            float bb[4] = {b0.x,b0.y,b0.z,b0.w};
#pragma unroll
            for (int i = 0; i < 8; i++)
#pragma unroll
                for (int j = 0; j < 4; j++) acc[i][j] = fmaf(a[i], bb[j], acc[i][j]);
        }
        __syncthreads();
    }
#pragma unroll
    for (int i = 0; i < 8; i++) {
        size_t off = (size_t)(bm + row0 + i) * N + bn + col0;
        float4 r = make_float4(acc[i][0], acc[i][1], acc[i][2], acc[i][3]);
        if (addsrc) {
            float4 av = *(const float4*)(addsrc + off);
            r.x += av.x; r.y += av.y; r.z += av.z; r.w += av.w;
        }
        *(float4*)(C + off) = r;
    }
}

// ---------------- depthwise causal conv k=3 + SiLU ----------------
__global__ void conv_silu_kernel(const float* __restrict__ cw, const float* __restrict__ cb)
{
    size_t idx = (size_t)blockIdx.x * 256 + threadIdx.x;   // over NTOK*DI
    int i = (int)(idx % DI);
    size_t t = idx / DI;
    int l = (int)(t % LSEQ);
    const float* base = g_xz + t * NXZ + i;                // xb = cols [0,384)
    float acc = cb[i];
    float w0 = cw[i*3+0], w1 = cw[i*3+1], w2 = cw[i*3+2];
    if (l >= 2) acc = fmaf(base[-2*NXZ], w0, acc);
    if (l >= 1) acc = fmaf(base[-1*NXZ], w1, acc);
    acc = fmaf(base[0], w2, acc);
    g_u[idx] = siluf_(acc);
}

// ---------------- x-proj (384->14) + dt GEMM (12->384) + softplus; warp/token ----------------
__global__ __launch_bounds__(256)
void proj_dt_kernel(const float* __restrict__ Wx, const float* __restrict__ Wdt,
                    const float* __restrict__ bdt)
{
    __shared__ float sWx[DI * NPROJ];    // 5376
    __shared__ float sWdt[DTR * DI];     // 4608
    __shared__ float sbdt[DI];
    for (int j = threadIdx.x; j < DI*NPROJ; j += 256) sWx[j] = Wx[j];
    for (int j = threadIdx.x; j < DTR*DI;  j += 256) sWdt[j] = Wdt[j];
    for (int j = threadIdx.x; j < DI;      j += 256) sbdt[j] = bdt[j];
    __syncthreads();

    int warp = threadIdx.x >> 5, lane = threadIdx.x & 31;
    size_t t = (size_t)blockIdx.x * 8 + warp;
    const float* urow = g_u + t * DI;
    float uv[12];
#pragma unroll
    for (int r = 0; r < 12; r++) uv[r] = urow[lane + 32*r];

    float pr[NPROJ];
#pragma unroll
    for (int j = 0; j < NPROJ; j++) {
        float s = 0.f;
#pragma unroll
        for (int r = 0; r < 12; r++) s = fmaf(uv[r], sWx[(lane + 32*r) * NPROJ + j], s);
#pragma unroll
        for (int o = 16; o; o >>= 1) s += __shfl_xor_sync(0xffffffffu, s, o);
        pr[j] = s;
    }
    if (lane == 0) { g_Bv[t] = pr[DTR]; g_Cv[t] = pr[DTR+1]; }

    float* dtrow = g_dt + t * DI;
#pragma unroll
    for (int r = 0; r < 12; r++) {
        int i = lane + 32*r;
        float s = sbdt[i];
#pragma unroll
        for (int k = 0; k < DTR; k++) s = fmaf(pr[k], sWdt[k*DI + i], s);
        dtrow[i] = softplusf_(s);
    }
}

// ---------------- scan pass 1: per-chunk (A-prod, end-state from h=0) ----------------
__global__ void scan1_kernel(const float* __restrict__ A_log)
{
    int idx = blockIdx.x * 256 + threadIdx.x;   // (b*NC + c)*DI + i
    int i = idx % DI;
    int c = (idx / DI) % NC;
    int b = idx / (DI * NC);
    float A = -expf(A_log[i]);
    size_t t0 = (size_t)b * LSEQ + (size_t)c * CL;
    float h = 0.f, ap = 1.f;
#pragma unroll 4
    for (int s = 0; s < CL; s++) {
        size_t t = t0 + s;
        float d  = g_dt[t * DI + i];
        float uu = g_u [t * DI + i];
        float dA = expf(d * A);
        h = fmaf(dA, h, d * g_Bv[t] * uu);
        ap *= dA;
    }
    g_ca[idx] = ap; g_ch[idx] = h;
}

// ---------------- scan pass 2: scan over chunk states (one thread per (b,i)) ----------------
__global__ void scan2_kernel()
{
    int idx = blockIdx.x * 256 + threadIdx.x;   // b*DI + i
    int i = idx % DI;
    int b = idx / DI;
    float h = 0.f;
    for (int c = 0; c < NC; c++) {
        int j = (b * NC + c) * DI + i;
        g_hi[j] = h;
        h = fmaf(g_ca[j], h, g_ch[j]);
    }
}

// ---------------- scan pass 3: recompute with correct init, gate, write y_pre ----------------
__global__ void scan3_kernel(const float* __restrict__ A_log, const float* __restrict__ Dw)
{
    int idx = blockIdx.x * 256 + threadIdx.x;
    int i = idx % DI;
    int c = (idx / DI) % NC;
    int b = idx / (DI * NC);
    float A = -expf(A_log[i]);
    float Dv = Dw[i];
    size_t t0 = (size_t)b * LSEQ + (size_t)c * CL;
    float h = g_hi[idx];
#pragma unroll 4
    for (int s = 0; s < CL; s++) {
        size_t t = t0 + s;
        float d  = g_dt[t * DI + i];
        float uu = g_u [t * DI + i];
        float dA = expf(d * A);
        h = fmaf(dA, h, d * g_Bv[t] * uu);
        float y = fmaf(h, g_Cv[t], uu * Dv);
        float z = g_xz[t * NXZ + DI + i];
        g_yp[t * DI + i] = y * siluf_(z);
    }
}

extern "C" void kernel_launch(void* const* d_in, const int* in_sizes, int n_in,
                              void* d_out, int out_size)
{
    const float* x      = (const float*)d_in[0];
    const float* ln_w   = (const float*)d_in[1];
    const float* ln_b   = (const float*)d_in[2];
    const float* W_in   = (const float*)d_in[3];
    const float* conv_w = (const float*)d_in[4];
    const float* conv_b = (const float*)d_in[5];
    const float* W_xprj = (const float*)d_in[6];
    const float* W_dt   = (const float*)d_in[7];
    const float* b_dt   = (const float*)d_in[8];
    const float* A_log  = (const float*)d_in[9];
    const float* Dw     = (const float*)d_in[10];
    const float* W_out  = (const float*)d_in[11];
    float* out = (float*)d_out;

    float *p_xn, *p_xz, *p_yp;
    cudaGetSymbolAddress((void**)&p_xn, g_xn);
    cudaGetSymbolAddress((void**)&p_xz, g_xz);
    cudaGetSymbolAddress((void**)&p_yp, g_yp);

    // 1. LayerNorm
    ln_kernel<<<NTOK/8, 256>>>(x, ln_w, ln_b);

    // 2. xz = xn @ W_in   [NTOK,192]x[192,768]
    {
        dim3 grid(NXZ/64, NTOK/128);
        gemm_kernel<<<grid, 256>>>(p_xn, W_in, nullptr, p_xz, NTOK, NXZ, CDIM);
    }

    // 3. u = silu(causal depthwise conv(xb))
    conv_silu_kernel<<<(NTOK*(size_t)DI)/256, 256>>>(conv_w, conv_b);

    // 4. proj + dt + softplus + B/C extraction
    proj_dt_kernel<<<NTOK/8, 256>>>(W_xprj, W_dt, b_dt);

    // 5-7. chunked selective scan
    scan1_kernel<<<(NB*NC*DI)/256, 256>>>(A_log);
    scan2_kernel<<<(NB*DI)/256, 256>>>();
    scan3_kernel<<<(NB*NC*DI)/256, 256>>>(A_log, Dw);

    // 8. out = y_pre @ W_out + x   [NTOK,384]x[384,192]
    {
        dim3 grid(CDIM/64, NTOK/128);
        gemm_kernel<<<grid, 256>>>(p_yp, W_out, x, out, NTOK, CDIM, DI);
    }
}

// round 4
// speedup vs baseline: 1.6863x; 1.6863x over previous
#include <cuda_runtime.h>
#include <cuda_bf16.h>
#include <cstdint>
#include <cstddef>

// Problem constants
#define NB   16
#define LSEQ 9216
#define NTOK 147456          // NB*LSEQ
#define CDIM 192
#define DI   384             // d_inner
#define NXZ  768             // 2*DI
#define DTR  12              // dt_rank
#define NPROJ 14             // dt_rank + 2*d_state
#define NC   36              // scan chunks per sequence
#define CL   256             // chunk length (NC*CL = LSEQ)

// -------- scratch (device globals; no allocation allowed) --------
__device__ __nv_bfloat16  g_xnb[(size_t)NTOK * CDIM];  // layernorm output (bf16)
__device__ __nv_bfloat16  g_xz [(size_t)NTOK * NXZ];   // cols [0,384)=xb, [384,768)=z
__device__ __nv_bfloat16  g_u  [(size_t)NTOK * DI];    // silu(conv(xb))
__device__ __nv_bfloat162 g_ad [(size_t)NTOK * DI];    // {dA, dBu} per (t,i)
__device__ __nv_bfloat16  g_yp [(size_t)NTOK * DI];    // gated scan output
__device__ __nv_bfloat16  g_Wt [NXZ * CDIM];           // W_in^T  [768,192] K-major
__device__ __nv_bfloat16  g_WoT[CDIM * DI];            // W_out^T [192,384] K-major
__device__ float g_Cv[NTOK];
__device__ float g_ca[NB * NC * DI];
__device__ float g_ch[NB * NC * DI];
__device__ float g_hi[NB * NC * DI];

__device__ __forceinline__ float sigmoidf_(float v) { return 1.0f / (1.0f + expf(-v)); }
__device__ __forceinline__ float siluf_(float v)    { return v * sigmoidf_(v); }
__device__ __forceinline__ float softplusf_(float v){ return v > 20.0f ? v : log1pf(expf(v)); }

__device__ __forceinline__ uint32_t smem_u32(const void* p) {
    uint32_t a;
    asm("{ .reg .u64 t; cvta.to.shared.u64 t, %1; cvt.u32.u64 %0, t; }" : "=r"(a) : "l"(p));
    return a;
}
__device__ __forceinline__ void ldsm_x4(uint32_t addr, uint32_t& r0, uint32_t& r1,
                                        uint32_t& r2, uint32_t& r3) {
    asm volatile("ldmatrix.sync.aligned.m8n8.x4.shared.b16 {%0,%1,%2,%3}, [%4];"
                 : "=r"(r0), "=r"(r1), "=r"(r2), "=r"(r3) : "r"(addr));
}
__device__ __forceinline__ void mma_bf16(float* c, const uint32_t* a, uint32_t b0, uint32_t b1) {
    asm volatile("mma.sync.aligned.m16n8k16.row.col.f32.bf16.bf16.f32 "
                 "{%0,%1,%2,%3}, {%4,%5,%6,%7}, {%8,%9}, {%0,%1,%2,%3};"
                 : "+f"(c[0]), "+f"(c[1]), "+f"(c[2]), "+f"(c[3])
                 : "r"(a[0]), "r"(a[1]), "r"(a[2]), "r"(a[3]), "r"(b0), "r"(b1));
}

// ================= weight transposes (tiny) =================
__global__ void wt_kernel(const float* __restrict__ W_in) {
    int i = blockIdx.x * 256 + threadIdx.x;          // over NXZ*CDIM
    if (i >= NXZ * CDIM) return;
    int n = i / CDIM, k = i % CDIM;
    g_Wt[i] = __float2bfloat16_rn(W_in[(size_t)k * NXZ + n]);
}
__global__ void wo_kernel(const float* __restrict__ W_out) {
    int i = blockIdx.x * 256 + threadIdx.x;          // over CDIM*DI
    if (i >= CDIM * DI) return;
    int n = i / DI, k = i % DI;
    g_WoT[i] = __float2bfloat16_rn(W_out[(size_t)k * CDIM + n]);
}

// ================= LayerNorm -> bf16 =================
__global__ void ln_kernel(const float* __restrict__ x,
                          const float* __restrict__ w,
                          const float* __restrict__ b)
{
    int warp = threadIdx.x >> 5, lane = threadIdx.x & 31;
    size_t t = (size_t)blockIdx.x * 8 + warp;
    const float* row = x + t * CDIM;
    float v[6];
    float s = 0.f;
#pragma unroll
    for (int r = 0; r < 6; r++) { v[r] = row[lane + 32*r]; s += v[r]; }
#pragma unroll
    for (int o = 16; o; o >>= 1) s += __shfl_xor_sync(0xffffffffu, s, o);
    float mu = s * (1.0f/192.0f);
    float q = 0.f;
#pragma unroll
    for (int r = 0; r < 6; r++) { float d = v[r] - mu; q += d*d; }
#pragma unroll
    for (int o = 16; o; o >>= 1) q += __shfl_xor_sync(0xffffffffu, q, o);
    float inv = rsqrtf(q * (1.0f/192.0f) + 1e-5f);
    __nv_bfloat16* out = g_xnb + t * CDIM;
#pragma unroll
    for (int r = 0; r < 6; r++) {
        int c = lane + 32*r;
        out[c] = __float2bfloat16_rn((v[r] - mu) * inv * w[c] + b[c]);
    }
}

// ================= HMMA bf16 GEMM =================
// C[M,N] = A[M,K](bf16 K-major) @ Bw[N,K](bf16 K-major)^T.  BM=128, BN=64,
// 256 threads (8 warps, 4x2 over M x N, warp tile 32x32). Whole K in SMEM.
// SMEM layout: 16B chunks, row r chunk c stored at (r*CH + (c ^ (r&7))).
template<int K, bool RESID>
__global__ __launch_bounds__(256)
void hmma_gemm(const __nv_bfloat16* __restrict__ A,
               const __nv_bfloat16* __restrict__ Bw,
               const float* __restrict__ resid,
               float* __restrict__ outf,
               __nv_bfloat16* __restrict__ outb,
               int N)
{
    constexpr int BM = 128, BN = 64;
    constexpr int CH = K / 8;                 // 16B chunks per row
    extern __shared__ char smem[];
    char* smA = smem;
    char* smB = smem + BM * CH * 16;
    int tid = threadIdx.x, wid = tid >> 5, lane = tid & 31;
    size_t bm = (size_t)blockIdx.y * BM;
    int bn = blockIdx.x * BN;

    // ---- load tiles ----
    for (int c = tid; c < BM * CH; c += 256) {
        int row = c / CH, ch = c % CH;
        uint4 v = *(const uint4*)(A + (bm + row) * K + ch * 8);
        *(uint4*)(smA + (row * CH + (ch ^ (row & 7))) * 16) = v;
    }
    for (int c = tid; c < BN * CH; c += 256) {
        int row = c / CH, ch = c % CH;
        uint4 v = *(const uint4*)(Bw + (size_t)(bn + row) * K + ch * 8);
        *(uint4*)(smB + (row * CH + (ch ^ (row & 7))) * 16) = v;
    }
    __syncthreads();

    uint32_t sa = smem_u32(smA), sbB = smem_u32(smB);
    int wm = wid & 3, wn = wid >> 2;
    int m0 = wm * 32, n0 = wn * 32;

    // ldmatrix lane addressing (row part precomputed)
    int a_row[2], b_row[4];
#pragma unroll
    for (int ti = 0; ti < 2; ti++) a_row[ti] = m0 + 16 * ti + (lane & 15);
#pragma unroll
    for (int j = 0; j < 4; j++)    b_row[j]  = n0 + 8 * j + (lane & 7);
    int a_klo = lane >> 4;        // 0..1 -> +8k
    int b_klo = lane >> 3;        // 0..3 -> chunk within 32k block

    float acc[2][4][4];
#pragma unroll
    for (int ti = 0; ti < 2; ti++)
#pragma unroll
        for (int j = 0; j < 4; j++)
#pragma unroll
            for (int e = 0; e < 4; e++) acc[ti][j][e] = 0.f;

#pragma unroll
    for (int kb = 0; kb < K / 32; kb++) {
        uint32_t br[4][4];
#pragma unroll
        for (int j = 0; j < 4; j++) {
            int r = b_row[j];
            uint32_t addr = sbB + (r * CH + ((4 * kb + b_klo) ^ (r & 7))) * 16;
            ldsm_x4(addr, br[j][0], br[j][1], br[j][2], br[j][3]);
        }
#pragma unroll
        for (int ks2 = 0; ks2 < 2; ks2++) {
            uint32_t ar[2][4];
#pragma unroll
            for (int ti = 0; ti < 2; ti++) {
                int r = a_row[ti];
                uint32_t addr = sa + (r * CH + ((4 * kb + 2 * ks2 + a_klo) ^ (r & 7))) * 16;
                ldsm_x4(addr, ar[ti][0], ar[ti][1], ar[ti][2], ar[ti][3]);
            }
#pragma unroll
            for (int ti = 0; ti < 2; ti++)
#pragma unroll
                for (int j = 0; j < 4; j++)
                    mma_bf16(acc[ti][j], ar[ti], br[j][2 * ks2], br[j][2 * ks2 + 1]);
        }
    }

    // ---- epilogue ----
#pragma unroll
    for (int ti = 0; ti < 2; ti++)
#pragma unroll
        for (int j = 0; j < 4; j++) {
            int row = m0 + 16 * ti + (lane >> 2);
            int col = bn + n0 + 8 * j + (lane & 3) * 2;
#pragma unroll
            for (int half = 0; half < 2; half++) {
                size_t off = (bm + row + 8 * half) * (size_t)N + col;
                float v0 = acc[ti][j][2 * half], v1 = acc[ti][j][2 * half + 1];
                if (RESID) {
                    float2 rv = *(const float2*)(resid + off);
                    *(float2*)(outf + off) = make_float2(v0 + rv.x, v1 + rv.y);
                } else {
                    __nv_bfloat162 p;
                    p.x = __float2bfloat16_rn(v0);
                    p.y = __float2bfloat16_rn(v1);
                    *(__nv_bfloat162*)(outb + off) = p;
                }
            }
        }
}

// ================= depthwise causal conv k=3 + SiLU =================
__global__ void conv_silu_kernel(const float* __restrict__ cw, const float* __restrict__ cb)
{
    size_t idx = (size_t)blockIdx.x * 256 + threadIdx.x;   // over NTOK*DI
    int i = (int)(idx % DI);
    size_t t = idx / DI;
    int l = (int)(t % LSEQ);
    const __nv_bfloat16* base = g_xz + t * NXZ + i;        // xb = cols [0,384)
    float acc = cb[i];
    float w0 = cw[i*3+0], w1 = cw[i*3+1], w2 = cw[i*3+2];
    if (l >= 2) acc = fmaf(__bfloat162float(base[-2*NXZ]), w0, acc);
    if (l >= 1) acc = fmaf(__bfloat162float(base[-1*NXZ]), w1, acc);
    acc = fmaf(__bfloat162float(base[0]), w2, acc);
    g_u[idx] = __float2bfloat16_rn(siluf_(acc));
}

// ================= x-proj + dt + softplus + {dA,dBu} precompute =================
__global__ __launch_bounds__(256)
void proj_dt_kernel(const float* __restrict__ Wx, const float* __restrict__ Wdt,
                    const float* __restrict__ bdt, const float* __restrict__ A_log)
{
    __shared__ float sWx[DI * NPROJ];
    __shared__ float sWdt[DTR * DI];
    __shared__ float sbdt[DI];
    __shared__ float sA[DI];
    for (int j = threadIdx.x; j < DI*NPROJ; j += 256) sWx[j] = Wx[j];
    for (int j = threadIdx.x; j < DTR*DI;  j += 256) sWdt[j] = Wdt[j];
    for (int j = threadIdx.x; j < DI;      j += 256) sbdt[j] = bdt[j];
    for (int j = threadIdx.x; j < DI;      j += 256) sA[j] = -expf(A_log[j]);
    __syncthreads();

    int warp = threadIdx.x >> 5, lane = threadIdx.x & 31;
    size_t t = (size_t)blockIdx.x * 8 + warp;
    const __nv_bfloat16* urow = g_u + t * DI;
    float uv[12];
#pragma unroll
    for (int r = 0; r < 12; r++) uv[r] = __bfloat162float(urow[lane + 32*r]);

    float pr[NPROJ];
#pragma unroll
    for (int j = 0; j < NPROJ; j++) {
        float s = 0.f;
#pragma unroll
        for (int r = 0; r < 12; r++) s = fmaf(uv[r], sWx[(lane + 32*r) * NPROJ + j], s);
#pragma unroll
        for (int o = 16; o; o >>= 1) s += __shfl_xor_sync(0xffffffffu, s, o);
        pr[j] = s;
    }
    float Bv = pr[DTR];
    if (lane == 0) g_Cv[t] = pr[DTR+1];

    __nv_bfloat162* adrow = g_ad + t * DI;
#pragma unroll
    for (int r = 0; r < 12; r++) {
        int i = lane + 32*r;
        float s = sbdt[i];
#pragma unroll
        for (int k = 0; k < DTR; k++) s = fmaf(pr[k], sWdt[k*DI + i], s);
        float dt = softplusf_(s);
        float dA = expf(dt * sA[i]);
        float dbu = dt * Bv * uv[r];
        __nv_bfloat162 p;
        p.x = __float2bfloat16_rn(dA);
        p.y = __float2bfloat16_rn(dbu);
        adrow[i] = p;
    }
}

// ================= chunked selective scan (no exp: pure FMA streaming) =================
__global__ void scan1_kernel()
{
    int idx = blockIdx.x * 256 + threadIdx.x;   // (b*NC + c)*DI + i
    int i = idx % DI;
    int c = (idx / DI) % NC;
    int b = idx / (DI * NC);
    size_t t0 = (size_t)b * LSEQ + (size_t)c * CL;
    float h = 0.f, ap = 1.f;
#pragma unroll 4
    for (int s = 0; s < CL; s++) {
        __nv_bfloat162 p = g_ad[(t0 + s) * DI + i];
        float dA = __bfloat162float(p.x);
        h = fmaf(dA, h, __bfloat162float(p.y));
        ap *= dA;
    }
    g_ca[idx] = ap; g_ch[idx] = h;
}

__global__ void scan2_kernel()
{
    int idx = blockIdx.x * 256 + threadIdx.x;   // b*DI + i
    int i = idx % DI;
    int b = idx / DI;
    float h = 0.f;
    for (int c = 0; c < NC; c++) {
        int j = (b * NC + c) * DI + i;
        g_hi[j] = h;
        h = fmaf(g_ca[j], h, g_ch[j]);
    }
}

__global__ void scan3_kernel(const float* __restrict__ Dw)
{
    int idx = blockIdx.x * 256 + threadIdx.x;
    int i = idx % DI;
    int c = (idx / DI) % NC;
    int b = idx / (DI * NC);
    float Dv = Dw[i];
    size_t t0 = (size_t)b * LSEQ + (size_t)c * CL;
    float h = g_hi[idx];
#pragma unroll 4
    for (int s = 0; s < CL; s++) {
        size_t t = t0 + s;
        __nv_bfloat162 p = g_ad[t * DI + i];
        h = fmaf(__bfloat162float(p.x), h, __bfloat162float(p.y));
        float uu = __bfloat162float(g_u[t * DI + i]);
        float y = fmaf(h, g_Cv[t], uu * Dv);
        float z = __bfloat162float(g_xz[t * NXZ + DI + i]);
        g_yp[t * DI + i] = __float2bfloat16_rn(y * siluf_(z));
    }
}

extern "C" void kernel_launch(void* const* d_in, const int* in_sizes, int n_in,
                              void* d_out, int out_size)
{
    const float* x      = (const float*)d_in[0];
    const float* ln_w   = (const float*)d_in[1];
    const float* ln_b   = (const float*)d_in[2];
    const float* W_in   = (const float*)d_in[3];
    const float* conv_w = (const float*)d_in[4];
    const float* conv_b = (const float*)d_in[5];
    const float* W_xprj = (const float*)d_in[6];
    const float* W_dt   = (const float*)d_in[7];
    const float* b_dt   = (const float*)d_in[8];
    const float* A_log  = (const float*)d_in[9];
    const float* Dw     = (const float*)d_in[10];
    const float* W_out  = (const float*)d_in[11];
    float* out = (float*)d_out;

    __nv_bfloat16 *p_xnb, *p_xz, *p_yp, *p_Wt, *p_WoT;
    cudaGetSymbolAddress((void**)&p_xnb, g_xnb);
    cudaGetSymbolAddress((void**)&p_xz,  g_xz);
    cudaGetSymbolAddress((void**)&p_yp,  g_yp);
    cudaGetSymbolAddress((void**)&p_Wt,  g_Wt);
    cudaGetSymbolAddress((void**)&p_WoT, g_WoT);

    const int SM1 = (128 + 64) * (192 / 8) * 16;   // 73728
    const int SM3 = (128 + 64) * (384 / 8) * 16;   // 147456
    cudaFuncSetAttribute(hmma_gemm<192,false>,
                         cudaFuncAttributeMaxDynamicSharedMemorySize, SM1);
    cudaFuncSetAttribute(hmma_gemm<384,true>,
                         cudaFuncAttributeMaxDynamicSharedMemorySize, SM3);

    // 0. weight transposes -> bf16 K-major
    wt_kernel<<<(NXZ*CDIM + 255)/256, 256>>>(W_in);
    wo_kernel<<<(CDIM*DI + 255)/256, 256>>>(W_out);

    // 1. LayerNorm -> bf16
    ln_kernel<<<NTOK/8, 256>>>(x, ln_w, ln_b);

    // 2. xz = xn @ W_in  (HMMA bf16): [NTOK,192] x [192,768] -> bf16
    {
        dim3 grid(NXZ/64, NTOK/128);
        hmma_gemm<192,false><<<grid, 256, SM1>>>(p_xnb, p_Wt, nullptr, nullptr, p_xz, NXZ);
    }

    // 3. u = silu(causal depthwise conv(xb))
    conv_silu_kernel<<<(NTOK*(size_t)DI)/256, 256>>>(conv_w, conv_b);

    // 4. proj + dt + softplus + {dA,dBu} precompute
    proj_dt_kernel<<<NTOK/8, 256>>>(W_xprj, W_dt, b_dt, A_log);

    // 5-7. chunked selective scan
    scan1_kernel<<<(NB*NC*DI)/256, 256>>>();
    scan2_kernel<<<(NB*DI)/256, 256>>>();
    scan3_kernel<<<(NB*NC*DI)/256, 256>>>(Dw);

    // 8. out = yp @ W_out + x  (HMMA bf16): [NTOK,384] x [384,192] -> fp32 + resid
    {
        dim3 grid(CDIM/64, NTOK/128);
        hmma_gemm<384,true><<<grid, 256, SM3>>>(p_yp, p_WoT, x, out, nullptr, CDIM);
    }
}

// round 5
// speedup vs baseline: 1.8753x; 1.1120x over previous
#include <cuda_runtime.h>
#include <cuda_bf16.h>
#include <cstdint>
#include <cstddef>

// Problem constants
#define NB   16
#define LSEQ 9216
#define NTOK 147456          // NB*LSEQ
#define CDIM 192
#define DI   384             // d_inner
#define NXZ  768             // 2*DI
#define DTR  12              // dt_rank
#define NPROJ 14             // dt_rank + 2*d_state
#define NC   36              // scan chunks per sequence
#define CL   256             // chunk length (NC*CL = LSEQ)

// -------- scratch (device globals; no allocation allowed) --------
__device__ __nv_bfloat16  g_xnb[(size_t)NTOK * CDIM];  // layernorm output (bf16)
__device__ __nv_bfloat16  g_xz [(size_t)NTOK * NXZ];   // cols [0,384)=xb, [384,768)=z
__device__ __nv_bfloat16  g_u  [(size_t)NTOK * DI];    // silu(conv(xb))
__device__ __nv_bfloat162 g_ad [(size_t)NTOK * DI];    // {dA, dBu} per (t,i)
__device__ __nv_bfloat16  g_yp [(size_t)NTOK * DI];    // gated scan output
__device__ __nv_bfloat16  g_Wt [NXZ * CDIM];           // W_in^T  [768,192] K-major
__device__ __nv_bfloat16  g_WoT[CDIM * DI];            // W_out^T [192,384] K-major
__device__ float g_Cv[NTOK];
__device__ float g_ca[NB * NC * DI];
__device__ float g_ch[NB * NC * DI];
__device__ float g_hi[NB * NC * DI];

__device__ __forceinline__ float sigmoidf_(float v) { return 1.0f / (1.0f + expf(-v)); }
__device__ __forceinline__ float siluf_(float v)    { return v * sigmoidf_(v); }
__device__ __forceinline__ float softplusf_(float v){ return v > 20.0f ? v : log1pf(expf(v)); }

__device__ __forceinline__ uint32_t smem_u32(const void* p) {
    uint32_t a;
    asm("{ .reg .u64 t; cvta.to.shared.u64 t, %1; cvt.u32.u64 %0, t; }" : "=r"(a) : "l"(p));
    return a;
}
__device__ __forceinline__ void ldsm_x4(uint32_t addr, uint32_t& r0, uint32_t& r1,
                                        uint32_t& r2, uint32_t& r3) {
    asm volatile("ldmatrix.sync.aligned.m8n8.x4.shared.b16 {%0,%1,%2,%3}, [%4];"
                 : "=r"(r0), "=r"(r1), "=r"(r2), "=r"(r3) : "r"(addr));
}
__device__ __forceinline__ void mma_bf16(float* c, const uint32_t* a, uint32_t b0, uint32_t b1) {
    asm volatile("mma.sync.aligned.m16n8k16.row.col.f32.bf16.bf16.f32 "
                 "{%0,%1,%2,%3}, {%4,%5,%6,%7}, {%8,%9}, {%0,%1,%2,%3};"
                 : "+f"(c[0]), "+f"(c[1]), "+f"(c[2]), "+f"(c[3])
                 : "r"(a[0]), "r"(a[1]), "r"(a[2]), "r"(a[3]), "r"(b0), "r"(b1));
}
__device__ __forceinline__ void cp16(uint32_t s, const void* g) {
    asm volatile("cp.async.cg.shared.global [%0], [%1], 16;" :: "r"(s), "l"(g));
}

// ================= weight transposes (tiny) =================
__global__ void wt_kernel(const float* __restrict__ W_in) {
    int i = blockIdx.x * 256 + threadIdx.x;
    if (i >= NXZ * CDIM) return;
    int n = i / CDIM, k = i % CDIM;
    g_Wt[i] = __float2bfloat16_rn(W_in[(size_t)k * NXZ + n]);
}
__global__ void wo_kernel(const float* __restrict__ W_out) {
    int i = blockIdx.x * 256 + threadIdx.x;
    if (i >= CDIM * DI) return;
    int n = i / DI, k = i % DI;
    g_WoT[i] = __float2bfloat16_rn(W_out[(size_t)k * CDIM + n]);
}

// ================= LayerNorm -> bf16 =================
__global__ void ln_kernel(const float* __restrict__ x,
                          const float* __restrict__ w,
                          const float* __restrict__ b)
{
    int warp = threadIdx.x >> 5, lane = threadIdx.x & 31;
    size_t t = (size_t)blockIdx.x * 8 + warp;
    const float* row = x + t * CDIM;
    float v[6];
    float s = 0.f;
#pragma unroll
    for (int r = 0; r < 6; r++) { v[r] = row[lane + 32*r]; s += v[r]; }
#pragma unroll
    for (int o = 16; o; o >>= 1) s += __shfl_xor_sync(0xffffffffu, s, o);
    float mu = s * (1.0f/192.0f);
    float q = 0.f;
#pragma unroll
    for (int r = 0; r < 6; r++) { float d = v[r] - mu; q += d*d; }
#pragma unroll
    for (int o = 16; o; o >>= 1) q += __shfl_xor_sync(0xffffffffu, q, o);
    float inv = rsqrtf(q * (1.0f/192.0f) + 1e-5f);
    __nv_bfloat16* out = g_xnb + t * CDIM;
#pragma unroll
    for (int r = 0; r < 6; r++) {
        int c = lane + 32*r;
        out[c] = __float2bfloat16_rn((v[r] - mu) * inv * w[c] + b[c]);
    }
}

// ================= pipelined HMMA bf16 GEMM =================
// C[M,N] = A[M,K](bf16 K-major) @ Bw[N,K](bf16 K-major)^T.
// BM=128, BN=64, BK=64, 2-stage cp.async double buffer, 256 threads,
// 8 warps (4x2), warp tile 32x32. SMEM: 16B chunks, chunk c of row r at
// (r*8 + (c ^ (r&7))).
template<bool RESID>
__global__ __launch_bounds__(256)
void hmma_gemm(const __nv_bfloat16* __restrict__ A,
               const __nv_bfloat16* __restrict__ Bw,
               const float* __restrict__ resid,
               float* __restrict__ outf,
               __nv_bfloat16* __restrict__ outb,
               int N, int K)
{
    constexpr int BM = 128, BN = 64, BK = 64;
    constexpr int ABYTES = BM * BK * 2;              // 16384
    constexpr int STAGE  = (BM + BN) * BK * 2;       // 24576
    extern __shared__ char smem[];
    int tid = threadIdx.x, wid = tid >> 5, lane = tid & 31;
    size_t bm = (size_t)blockIdx.y * BM;
    int bn = blockIdx.x * BN;
    int m0 = (wid & 3) * 32, n0 = (wid >> 2) * 32;

    uint32_t smem_base = smem_u32(smem);

    // per-thread load slots (fixed across stages)
    int arow[4], ach[4];
#pragma unroll
    for (int it = 0; it < 4; it++) {
        int c = tid + it * 256;
        arow[it] = c >> 3; ach[it] = c & 7;
    }
    int brow[2], bch[2];
#pragma unroll
    for (int it = 0; it < 2; it++) {
        int c = tid + it * 256;
        brow[it] = c >> 3; bch[it] = c & 7;
    }

    auto load_stage = [&](int st, int k0) {
        uint32_t sbase = smem_base + st * STAGE;
#pragma unroll
        for (int it = 0; it < 4; it++) {
            int row = arow[it], ch = ach[it];
            cp16(sbase + (uint32_t)(((row << 3) + (ch ^ (row & 7))) * 16),
                 A + (bm + row) * K + k0 + ch * 8);
        }
#pragma unroll
        for (int it = 0; it < 2; it++) {
            int row = brow[it], ch = bch[it];
            cp16(sbase + ABYTES + (uint32_t)(((row << 3) + (ch ^ (row & 7))) * 16),
                 Bw + (size_t)(bn + row) * K + k0 + ch * 8);
        }
        asm volatile("cp.async.commit_group;");
    };

    float acc[2][4][4];
#pragma unroll
    for (int ti = 0; ti < 2; ti++)
#pragma unroll
        for (int j = 0; j < 4; j++)
#pragma unroll
            for (int e = 0; e < 4; e++) acc[ti][j][e] = 0.f;

    int a_r[2], b_r[4];
#pragma unroll
    for (int ti = 0; ti < 2; ti++) a_r[ti] = m0 + 16 * ti + (lane & 15);
#pragma unroll
    for (int j = 0; j < 4; j++)    b_r[j]  = n0 + 8 * j + (lane & 7);
    int a_klo = lane >> 4;   // 0..1
    int b_klo = lane >> 3;   // 0..3

    int KC = K / BK;
    load_stage(0, 0);
    for (int kc = 0; kc < KC; kc++) {
        if (kc + 1 < KC) {
            load_stage((kc + 1) & 1, (kc + 1) * BK);
            asm volatile("cp.async.wait_group 1;");
        } else {
            asm volatile("cp.async.wait_group 0;");
        }
        __syncthreads();

        uint32_t sa = smem_base + (kc & 1) * STAGE;
        uint32_t sb = sa + ABYTES;
#pragma unroll
        for (int kb2 = 0; kb2 < 2; kb2++) {          // two 32-k sub-blocks
            uint32_t br[4][4];
#pragma unroll
            for (int j = 0; j < 4; j++) {
                int r = b_r[j];
                uint32_t addr = sb + (uint32_t)(((r << 3) + ((kb2 * 4 + b_klo) ^ (r & 7))) * 16);
                ldsm_x4(addr, br[j][0], br[j][1], br[j][2], br[j][3]);
            }
#pragma unroll
            for (int ks2 = 0; ks2 < 2; ks2++) {      // two k16 steps
                uint32_t ar[2][4];
#pragma unroll
                for (int ti = 0; ti < 2; ti++) {
                    int r = a_r[ti];
                    uint32_t addr = sa + (uint32_t)(((r << 3) +
                        ((kb2 * 4 + ks2 * 2 + a_klo) ^ (r & 7))) * 16);
                    ldsm_x4(addr, ar[ti][0], ar[ti][1], ar[ti][2], ar[ti][3]);
                }
#pragma unroll
                for (int ti = 0; ti < 2; ti++)
#pragma unroll
                    for (int j = 0; j < 4; j++)
                        mma_bf16(acc[ti][j], ar[ti], br[j][2 * ks2], br[j][2 * ks2 + 1]);
            }
        }
        __syncthreads();
    }

    // ---- epilogue ----
#pragma unroll
    for (int ti = 0; ti < 2; ti++)
#pragma unroll
        for (int j = 0; j < 4; j++) {
            int row = m0 + 16 * ti + (lane >> 2);
            int col = bn + n0 + 8 * j + (lane & 3) * 2;
#pragma unroll
            for (int half = 0; half < 2; half++) {
                size_t off = (bm + row + 8 * half) * (size_t)N + col;
                float v0 = acc[ti][j][2 * half], v1 = acc[ti][j][2 * half + 1];
                if (RESID) {
                    float2 rv = *(const float2*)(resid + off);
                    *(float2*)(outf + off) = make_float2(v0 + rv.x, v1 + rv.y);
                } else {
                    __nv_bfloat162 p;
                    p.x = __float2bfloat16_rn(v0);
                    p.y = __float2bfloat16_rn(v1);
                    *(__nv_bfloat162*)(outb + off) = p;
                }
            }
        }
}

// ================= depthwise causal conv k=3 + SiLU =================
__global__ void conv_silu_kernel(const float* __restrict__ cw, const float* __restrict__ cb)
{
    size_t idx = (size_t)blockIdx.x * 256 + threadIdx.x;   // over NTOK*DI
    int i = (int)(idx % DI);
    size_t t = idx / DI;
    int l = (int)(t % LSEQ);
    const __nv_bfloat16* base = g_xz + t * NXZ + i;        // xb = cols [0,384)
    float acc = cb[i];
    float w0 = cw[i*3+0], w1 = cw[i*3+1], w2 = cw[i*3+2];
    if (l >= 2) acc = fmaf(__bfloat162float(base[-2*NXZ]), w0, acc);
    if (l >= 1) acc = fmaf(__bfloat162float(base[-1*NXZ]), w1, acc);
    acc = fmaf(__bfloat162float(base[0]), w2, acc);
    g_u[idx] = __float2bfloat16_rn(siluf_(acc));
}

// ================= x-proj + dt + softplus + {dA,dBu} precompute =================
__global__ __launch_bounds__(256)
void proj_dt_kernel(const float* __restrict__ Wx, const float* __restrict__ Wdt,
                    const float* __restrict__ bdt, const float* __restrict__ A_log)
{
    __shared__ float sWxT[NPROJ * DI];   // transposed: [j][i] -> lane-consecutive
    __shared__ float sWdt[DTR * DI];
    __shared__ float sbdt[DI];
    __shared__ float sA[DI];
    for (int idx = threadIdx.x; idx < DI*NPROJ; idx += 256) {
        int i = idx / NPROJ, j = idx % NPROJ;
        sWxT[j * DI + i] = Wx[idx];
    }
    for (int j = threadIdx.x; j < DTR*DI; j += 256) sWdt[j] = Wdt[j];
    for (int j = threadIdx.x; j < DI;     j += 256) sbdt[j] = bdt[j];
    for (int j = threadIdx.x; j < DI;     j += 256) sA[j] = -expf(A_log[j]);
    __syncthreads();

    int warp = threadIdx.x >> 5, lane = threadIdx.x & 31;
    size_t t = (size_t)blockIdx.x * 8 + warp;
    const __nv_bfloat16* urow = g_u + t * DI;
    float uv[12];
#pragma unroll
    for (int r = 0; r < 12; r++) uv[r] = __bfloat162float(urow[lane + 32*r]);

    float pr[NPROJ];
#pragma unroll
    for (int j = 0; j < NPROJ; j++) {
        float s = 0.f;
#pragma unroll
        for (int r = 0; r < 12; r++) s = fmaf(uv[r], sWxT[j * DI + lane + 32*r], s);
#pragma unroll
        for (int o = 16; o; o >>= 1) s += __shfl_xor_sync(0xffffffffu, s, o);
        pr[j] = s;
    }
    float Bv = pr[DTR];
    if (lane == 0) g_Cv[t] = pr[DTR+1];

    __nv_bfloat162* adrow = g_ad + t * DI;
#pragma unroll
    for (int r = 0; r < 12; r++) {
        int i = lane + 32*r;
        float s = sbdt[i];
#pragma unroll
        for (int k = 0; k < DTR; k++) s = fmaf(pr[k], sWdt[k*DI + i], s);
        float dt = softplusf_(s);
        float dA = expf(dt * sA[i]);
        float dbu = dt * Bv * uv[r];
        __nv_bfloat162 p;
        p.x = __float2bfloat16_rn(dA);
        p.y = __float2bfloat16_rn(dbu);
        adrow[i] = p;
    }
}

// ================= chunked selective scan (pure FMA streaming) =================
__global__ void scan1_kernel()
{
    int idx = blockIdx.x * 256 + threadIdx.x;   // (b*NC + c)*DI + i
    int i = idx % DI;
    int c = (idx / DI) % NC;
    int b = idx / (DI * NC);
    size_t t0 = (size_t)b * LSEQ + (size_t)c * CL;
    float h = 0.f, ap = 1.f;
#pragma unroll 4
    for (int s = 0; s < CL; s++) {
        __nv_bfloat162 p = g_ad[(t0 + s) * DI + i];
        float dA = __bfloat162float(p.x);
        h = fmaf(dA, h, __bfloat162float(p.y));
        ap *= dA;
    }
    g_ca[idx] = ap; g_ch[idx] = h;
}

__global__ void scan2_kernel()
{
    int idx = blockIdx.x * 256 + threadIdx.x;   // b*DI + i
    int i = idx % DI;
    int b = idx / DI;
    float h = 0.f;
    for (int c = 0; c < NC; c++) {
        int j = (b * NC + c) * DI + i;
        g_hi[j] = h;
        h = fmaf(g_ca[j], h, g_ch[j]);
    }
}

__global__ void scan3_kernel(const float* __restrict__ Dw)
{
    int idx = blockIdx.x * 256 + threadIdx.x;
    int i = idx % DI;
    int c = (idx / DI) % NC;
    int b = idx / (DI * NC);
    float Dv = Dw[i];
    size_t t0 = (size_t)b * LSEQ + (size_t)c * CL;
    float h = g_hi[idx];
#pragma unroll 4
    for (int s = 0; s < CL; s++) {
        size_t t = t0 + s;
        __nv_bfloat162 p = g_ad[t * DI + i];
        h = fmaf(__bfloat162float(p.x), h, __bfloat162float(p.y));
        float uu = __bfloat162float(g_u[t * DI + i]);
        float y = fmaf(h, g_Cv[t], uu * Dv);
        float z = __bfloat162float(g_xz[t * NXZ + DI + i]);
        g_yp[t * DI + i] = __float2bfloat16_rn(y * siluf_(z));
    }
}

extern "C" void kernel_launch(void* const* d_in, const int* in_sizes, int n_in,
                              void* d_out, int out_size)
{
    const float* x      = (const float*)d_in[0];
    const float* ln_w   = (const float*)d_in[1];
    const float* ln_b   = (const float*)d_in[2];
    const float* W_in   = (const float*)d_in[3];
    const float* conv_w = (const float*)d_in[4];
    const float* conv_b = (const float*)d_in[5];
    const float* W_xprj = (const float*)d_in[6];
    const float* W_dt   = (const float*)d_in[7];
    const float* b_dt   = (const float*)d_in[8];
    const float* A_log  = (const float*)d_in[9];
    const float* Dw     = (const float*)d_in[10];
    const float* W_out  = (const float*)d_in[11];
    float* out = (float*)d_out;

    __nv_bfloat16 *p_xnb, *p_xz, *p_yp, *p_Wt, *p_WoT;
    cudaGetSymbolAddress((void**)&p_xnb, g_xnb);
    cudaGetSymbolAddress((void**)&p_xz,  g_xz);
    cudaGetSymbolAddress((void**)&p_yp,  g_yp);
    cudaGetSymbolAddress((void**)&p_Wt,  g_Wt);
    cudaGetSymbolAddress((void**)&p_WoT, g_WoT);

    const int SMEM = 2 * (128 + 64) * 64 * 2;   // 49152
    cudaFuncSetAttribute(hmma_gemm<false>,
                         cudaFuncAttributeMaxDynamicSharedMemorySize, SMEM);
    cudaFuncSetAttribute(hmma_gemm<true>,
                         cudaFuncAttributeMaxDynamicSharedMemorySize, SMEM);

    // 0. weight transposes -> bf16 K-major
    wt_kernel<<<(NXZ*CDIM + 255)/256, 256>>>(W_in);
    wo_kernel<<<(CDIM*DI + 255)/256, 256>>>(W_out);

    // 1. LayerNorm -> bf16
    ln_kernel<<<NTOK/8, 256>>>(x, ln_w, ln_b);

    // 2. xz = xn @ W_in  (HMMA bf16): [NTOK,192] x [192,768] -> bf16
    {
        dim3 grid(NXZ/64, NTOK/128);
        hmma_gemm<false><<<grid, 256, SMEM>>>(p_xnb, p_Wt, nullptr, nullptr, p_xz, NXZ, CDIM);
    }

    // 3. u = silu(causal depthwise conv(xb))
    conv_silu_kernel<<<(NTOK*(size_t)DI)/256, 256>>>(conv_w, conv_b);

    // 4. proj + dt + softplus + {dA,dBu} precompute
    proj_dt_kernel<<<NTOK/8, 256>>>(W_xprj, W_dt, b_dt, A_log);

    // 5-7. chunked selective scan
    scan1_kernel<<<(NB*NC*DI)/256, 256>>>();
    scan2_kernel<<<(NB*DI)/256, 256>>>();
    scan3_kernel<<<(NB*NC*DI)/256, 256>>>(Dw);

    // 8. out = yp @ W_out + x  (HMMA bf16): [NTOK,384] x [384,192] -> fp32 + resid
    {
        dim3 grid(CDIM/64, NTOK/128);
        hmma_gemm<true><<<grid, 256, SMEM>>>(p_yp, p_WoT, x, out, nullptr, CDIM, DI);
    }
}

// round 6
// speedup vs baseline: 1.8966x; 1.0114x over previous
#include <cuda_runtime.h>
#include <cuda_bf16.h>
#include <cstdint>
#include <cstddef>

// Problem constants
#define NB   16
#define LSEQ 9216
#define NTOK 147456          // NB*LSEQ
#define CDIM 192
#define DI   384             // d_inner
#define NXZ  768             // 2*DI
#define DTR  12              // dt_rank
#define NPROJ 14             // dt_rank + 2*d_state
#define NC   36              // scan chunks per sequence
#define CL   256             // chunk length (NC*CL = LSEQ)

// -------- scratch (device globals; no allocation allowed) --------
__device__ __nv_bfloat16  g_xnb[(size_t)NTOK * CDIM];  // layernorm output (bf16)
__device__ __nv_bfloat16  g_xz [(size_t)NTOK * NXZ];   // cols [0,384)=xb, [384,768)=z
__device__ __nv_bfloat16  g_u  [(size_t)NTOK * DI];    // silu(conv(xb))
__device__ __nv_bfloat162 g_ad [(size_t)NTOK * DI];    // {dA, dBu} per (t,i)
__device__ __nv_bfloat16  g_yp [(size_t)NTOK * DI];    // gated scan output
__device__ __nv_bfloat16  g_Wt [NXZ * CDIM];           // W_in^T  [768,192] K-major
__device__ __nv_bfloat16  g_WoT[CDIM * DI];            // W_out^T [192,384] K-major
__device__ float g_Cv[NTOK];
__device__ float g_ca[NB * NC * DI];
__device__ float g_ch[NB * NC * DI];
__device__ float g_hi[NB * NC * DI];

__device__ __forceinline__ float sigmoidf_(float v) { return 1.0f / (1.0f + expf(-v)); }
__device__ __forceinline__ float siluf_(float v)    { return v * sigmoidf_(v); }
__device__ __forceinline__ float softplusf_(float v){ return v > 20.0f ? v : log1pf(expf(v)); }

__device__ __forceinline__ uint32_t smem_u32(const void* p) {
    uint32_t a;
    asm("{ .reg .u64 t; cvta.to.shared.u64 t, %1; cvt.u32.u64 %0, t; }" : "=r"(a) : "l"(p));
    return a;
}
__device__ __forceinline__ void ldsm_x4(uint32_t addr, uint32_t& r0, uint32_t& r1,
                                        uint32_t& r2, uint32_t& r3) {
    asm volatile("ldmatrix.sync.aligned.m8n8.x4.shared.b16 {%0,%1,%2,%3}, [%4];"
                 : "=r"(r0), "=r"(r1), "=r"(r2), "=r"(r3) : "r"(addr));
}
__device__ __forceinline__ void mma_bf16(float* c, const uint32_t* a, uint32_t b0, uint32_t b1) {
    asm volatile("mma.sync.aligned.m16n8k16.row.col.f32.bf16.bf16.f32 "
                 "{%0,%1,%2,%3}, {%4,%5,%6,%7}, {%8,%9}, {%0,%1,%2,%3};"
                 : "+f"(c[0]), "+f"(c[1]), "+f"(c[2]), "+f"(c[3])
                 : "r"(a[0]), "r"(a[1]), "r"(a[2]), "r"(a[3]), "r"(b0), "r"(b1));
}
__device__ __forceinline__ void cp16(uint32_t s, const void* g) {
    asm volatile("cp.async.cg.shared.global [%0], [%1], 16;" :: "r"(s), "l"(g));
}
__device__ __forceinline__ void wait_groups(int n) {
    if (n == 0)      asm volatile("cp.async.wait_group 0;");
    else if (n == 1) asm volatile("cp.async.wait_group 1;");
}

// ================= weight transposes (tiny, merged) =================
__global__ void wtrans_kernel(const float* __restrict__ W_in,
                              const float* __restrict__ W_out) {
    int i = blockIdx.x * 256 + threadIdx.x;
    if (i < NXZ * CDIM) {
        int n = i / CDIM, k = i % CDIM;
        g_Wt[i] = __float2bfloat16_rn(W_in[(size_t)k * NXZ + n]);
    }
    int j = i - NXZ * CDIM;
    if (j >= 0 && j < CDIM * DI) {
        int n = j / DI, k = j % DI;
        g_WoT[j] = __float2bfloat16_rn(W_out[(size_t)k * CDIM + n]);
    }
}

// ================= LayerNorm -> bf16 =================
__global__ void ln_kernel(const float* __restrict__ x,
                          const float* __restrict__ w,
                          const float* __restrict__ b)
{
    int warp = threadIdx.x >> 5, lane = threadIdx.x & 31;
    size_t t = (size_t)blockIdx.x * 8 + warp;
    const float* row = x + t * CDIM;
    float v[6];
    float s = 0.f;
#pragma unroll
    for (int r = 0; r < 6; r++) { v[r] = row[lane + 32*r]; s += v[r]; }
#pragma unroll
    for (int o = 16; o; o >>= 1) s += __shfl_xor_sync(0xffffffffu, s, o);
    float mu = s * (1.0f/192.0f);
    float q = 0.f;
#pragma unroll
    for (int r = 0; r < 6; r++) { float d = v[r] - mu; q += d*d; }
#pragma unroll
    for (int o = 16; o; o >>= 1) q += __shfl_xor_sync(0xffffffffu, q, o);
    float inv = rsqrtf(q * (1.0f/192.0f) + 1e-5f);
    __nv_bfloat16* out = g_xnb + t * CDIM;
#pragma unroll
    for (int r = 0; r < 6; r++) {
        int c = lane + 32*r;
        out[c] = __float2bfloat16_rn((v[r] - mu) * inv * w[c] + b[c]);
    }
}

// ================= pipelined HMMA bf16 GEMM (3-stage ring, 1 sync/iter) =====
// C[M,N] = A[M,K](bf16 K-major) @ Bw[N,K](bf16 K-major)^T.
// BM=128, BN=64, BK=64, 256 threads, 8 warps (4x2), warp tile 32x32.
template<int K, bool RESID>
__global__ __launch_bounds__(256, 3)
void hmma_gemm(const __nv_bfloat16* __restrict__ A,
               const __nv_bfloat16* __restrict__ Bw,
               const float* __restrict__ resid,
               float* __restrict__ outf,
               __nv_bfloat16* __restrict__ outb,
               int N)
{
    constexpr int BM = 128, BN = 64, BK = 64;
    constexpr int KC = K / BK;
    constexpr int RING = 3;
    constexpr int ABYTES = BM * BK * 2;              // 16384
    constexpr int STAGE  = (BM + BN) * BK * 2;       // 24576
    extern __shared__ char smem[];
    int tid = threadIdx.x, wid = tid >> 5, lane = tid & 31;
    size_t bm = (size_t)blockIdx.y * BM;
    int bn = blockIdx.x * BN;
    int m0 = (wid & 3) * 32, n0 = (wid >> 2) * 32;

    uint32_t smem_base = smem_u32(smem);

    // per-thread load slots (fixed across stages)
    int arow[4], ach[4];
#pragma unroll
    for (int it = 0; it < 4; it++) {
        int c = tid + it * 256;
        arow[it] = c >> 3; ach[it] = c & 7;
    }
    int brow[2], bch[2];
#pragma unroll
    for (int it = 0; it < 2; it++) {
        int c = tid + it * 256;
        brow[it] = c >> 3; bch[it] = c & 7;
    }

    auto load_stage = [&](int st, int k0) {
        uint32_t sbase = smem_base + st * STAGE;
#pragma unroll
        for (int it = 0; it < 4; it++) {
            int row = arow[it], ch = ach[it];
            cp16(sbase + (uint32_t)(((row << 3) + (ch ^ (row & 7))) * 16),
                 A + (bm + row) * K + k0 + ch * 8);
        }
#pragma unroll
        for (int it = 0; it < 2; it++) {
            int row = brow[it], ch = bch[it];
            cp16(sbase + ABYTES + (uint32_t)(((row << 3) + (ch ^ (row & 7))) * 16),
                 Bw + (size_t)(bn + row) * K + k0 + ch * 8);
        }
        asm volatile("cp.async.commit_group;");
    };

    float acc[2][4][4];
#pragma unroll
    for (int ti = 0; ti < 2; ti++)
#pragma unroll
        for (int j = 0; j < 4; j++)
#pragma unroll
            for (int e = 0; e < 4; e++) acc[ti][j][e] = 0.f;

    int a_r[2], b_r[4];
#pragma unroll
    for (int ti = 0; ti < 2; ti++) a_r[ti] = m0 + 16 * ti + (lane & 15);
#pragma unroll
    for (int j = 0; j < 4; j++)    b_r[j]  = n0 + 8 * j + (lane & 7);
    int a_klo = lane >> 4;   // 0..1
    int b_klo = lane >> 3;   // 0..3

    // prologue: 2 stages in flight
    load_stage(0, 0);
    load_stage(1, BK);

#pragma unroll
    for (int kc = 0; kc < KC; kc++) {
        wait_groups(kc >= KC - 1 ? 0 : 1);
        __syncthreads();
        if (kc + 2 < KC) load_stage((kc + 2) % RING, (kc + 2) * BK);

        uint32_t sa = smem_base + (kc % RING) * STAGE;
        uint32_t sb = sa + ABYTES;
#pragma unroll
        for (int kb2 = 0; kb2 < 2; kb2++) {          // two 32-k sub-blocks
            uint32_t br[4][4];
#pragma unroll
            for (int j = 0; j < 4; j++) {
                int r = b_r[j];
                uint32_t addr = sb + (uint32_t)(((r << 3) + ((kb2 * 4 + b_klo) ^ (r & 7))) * 16);
                ldsm_x4(addr, br[j][0], br[j][1], br[j][2], br[j][3]);
            }
#pragma unroll
            for (int ks2 = 0; ks2 < 2; ks2++) {      // two k16 steps
                uint32_t ar[2][4];
#pragma unroll
                for (int ti = 0; ti < 2; ti++) {
                    int r = a_r[ti];
                    uint32_t addr = sa + (uint32_t)(((r << 3) +
                        ((kb2 * 4 + ks2 * 2 + a_klo) ^ (r & 7))) * 16);
                    ldsm_x4(addr, ar[ti][0], ar[ti][1], ar[ti][2], ar[ti][3]);
                }
#pragma unroll
                for (int ti = 0; ti < 2; ti++)
#pragma unroll
                    for (int j = 0; j < 4; j++)
                        mma_bf16(acc[ti][j], ar[ti], br[j][2 * ks2], br[j][2 * ks2 + 1]);
            }
        }
    }

    // ---- epilogue ----
#pragma unroll
    for (int ti = 0; ti < 2; ti++)
#pragma unroll
        for (int j = 0; j < 4; j++) {
            int row = m0 + 16 * ti + (lane >> 2);
            int col = bn + n0 + 8 * j + (lane & 3) * 2;
#pragma unroll
            for (int half = 0; half < 2; half++) {
                size_t off = (bm + row + 8 * half) * (size_t)N + col;
                float v0 = acc[ti][j][2 * half], v1 = acc[ti][j][2 * half + 1];
                if (RESID) {
                    float2 rv = *(const float2*)(resid + off);
                    *(float2*)(outf + off) = make_float2(v0 + rv.x, v1 + rv.y);
                } else {
                    __nv_bfloat162 p;
                    p.x = __float2bfloat16_rn(v0);
                    p.y = __float2bfloat16_rn(v1);
                    *(__nv_bfloat162*)(outb + off) = p;
                }
            }
        }
}

// ==== fused: depthwise causal conv k=3 + SiLU + x-proj + dt + {dA,dBu} ====
__global__ __launch_bounds__(256)
void proj_dt_kernel(const float* __restrict__ Wx, const float* __restrict__ Wdt,
                    const float* __restrict__ bdt, const float* __restrict__ A_log,
                    const float* __restrict__ cw, const float* __restrict__ cb)
{
    __shared__ float sWxT[NPROJ * DI];   // transposed: [j][i] -> lane-consecutive
    __shared__ float sWdt[DTR * DI];
    __shared__ float sbdt[DI];
    __shared__ float sA[DI];
    __shared__ float scw[DI * 3];
    __shared__ float scb[DI];
    for (int idx = threadIdx.x; idx < DI*NPROJ; idx += 256) {
        int i = idx / NPROJ, j = idx % NPROJ;
        sWxT[j * DI + i] = Wx[idx];
    }
    for (int j = threadIdx.x; j < DTR*DI; j += 256) sWdt[j] = Wdt[j];
    for (int j = threadIdx.x; j < DI*3;   j += 256) scw[j] = cw[j];
    for (int j = threadIdx.x; j < DI;     j += 256) {
        sbdt[j] = bdt[j];
        sA[j]   = -expf(A_log[j]);
        scb[j]  = cb[j];
    }
    __syncthreads();

    int warp = threadIdx.x >> 5, lane = threadIdx.x & 31;
    size_t t = (size_t)blockIdx.x * 8 + warp;
    int l = (int)(t % LSEQ);
    const __nv_bfloat16* xb = g_xz + t * NXZ;   // xb = cols [0,384)

    // conv k=3 causal + SiLU (in-register u)
    float uv[12];
#pragma unroll
    for (int r = 0; r < 12; r++) {
        int i = lane + 32 * r;
        float acc = scb[i];
        if (l >= 2) acc = fmaf(__bfloat162float(xb[i - 2*NXZ]), scw[i*3+0], acc);
        if (l >= 1) acc = fmaf(__bfloat162float(xb[i - 1*NXZ]), scw[i*3+1], acc);
        acc = fmaf(__bfloat162float(xb[i]), scw[i*3+2], acc);
        uv[r] = siluf_(acc);
    }
    // persist u for scan3
    __nv_bfloat16* urow = g_u + t * DI;
#pragma unroll
    for (int r = 0; r < 12; r++) urow[lane + 32*r] = __float2bfloat16_rn(uv[r]);

    float pr[NPROJ];
#pragma unroll
    for (int j = 0; j < NPROJ; j++) {
        float s = 0.f;
#pragma unroll
        for (int r = 0; r < 12; r++) s = fmaf(uv[r], sWxT[j * DI + lane + 32*r], s);
#pragma unroll
        for (int o = 16; o; o >>= 1) s += __shfl_xor_sync(0xffffffffu, s, o);
        pr[j] = s;
    }
    float Bv = pr[DTR];
    if (lane == 0) g_Cv[t] = pr[DTR+1];

    __nv_bfloat162* adrow = g_ad + t * DI;
#pragma unroll
    for (int r = 0; r < 12; r++) {
        int i = lane + 32*r;
        float s = sbdt[i];
#pragma unroll
        for (int k = 0; k < DTR; k++) s = fmaf(pr[k], sWdt[k*DI + i], s);
        float dt = softplusf_(s);
        float dA = expf(dt * sA[i]);
        float dbu = dt * Bv * uv[r];
        __nv_bfloat162 p;
        p.x = __float2bfloat16_rn(dA);
        p.y = __float2bfloat16_rn(dbu);
        adrow[i] = p;
    }
}

// ================= chunked selective scan (pure FMA streaming) =================
__global__ void scan1_kernel()
{
    int idx = blockIdx.x * 256 + threadIdx.x;   // (b*NC + c)*DI + i
    int i = idx % DI;
    int c = (idx / DI) % NC;
    int b = idx / (DI * NC);
    size_t t0 = (size_t)b * LSEQ + (size_t)c * CL;
    float h = 0.f, ap = 1.f;
#pragma unroll 4
    for (int s = 0; s < CL; s++) {
        __nv_bfloat162 p = g_ad[(t0 + s) * DI + i];
        float dA = __bfloat162float(p.x);
        h = fmaf(dA, h, __bfloat162float(p.y));
        ap *= dA;
    }
    g_ca[idx] = ap; g_ch[idx] = h;
}

__global__ void scan2_kernel()
{
    int idx = blockIdx.x * 256 + threadIdx.x;   // b*DI + i
    int i = idx % DI;
    int b = idx / DI;
    float h = 0.f;
    for (int c = 0; c < NC; c++) {
        int j = (b * NC + c) * DI + i;
        g_hi[j] = h;
        h = fmaf(g_ca[j], h, g_ch[j]);
    }
}

__global__ void scan3_kernel(const float* __restrict__ Dw)
{
    int idx = blockIdx.x * 256 + threadIdx.x;
    int i = idx % DI;
    int c = (idx / DI) % NC;
    int b = idx / (DI * NC);
    float Dv = Dw[i];
    size_t t0 = (size_t)b * LSEQ + (size_t)c * CL;
    float h = g_hi[idx];
#pragma unroll 4
    for (int s = 0; s < CL; s++) {
        size_t t = t0 + s;
        __nv_bfloat162 p = g_ad[t * DI + i];
        h = fmaf(__bfloat162float(p.x), h, __bfloat162float(p.y));
        float uu = __bfloat162float(g_u[t * DI + i]);
        float y = fmaf(h, g_Cv[t], uu * Dv);
        float z = __bfloat162float(g_xz[t * NXZ + DI + i]);
        g_yp[t * DI + i] = __float2bfloat16_rn(y * siluf_(z));
    }
}

extern "C" void kernel_launch(void* const* d_in, const int* in_sizes, int n_in,
                              void* d_out, int out_size)
{
    const float* x      = (const float*)d_in[0];
    const float* ln_w   = (const float*)d_in[1];
    const float* ln_b   = (const float*)d_in[2];
    const float* W_in   = (const float*)d_in[3];
    const float* conv_w = (const float*)d_in[4];
    const float* conv_b = (const float*)d_in[5];
    const float* W_xprj = (const float*)d_in[6];
    const float* W_dt   = (const float*)d_in[7];
    const float* b_dt   = (const float*)d_in[8];
    const float* A_log  = (const float*)d_in[9];
    const float* Dw     = (const float*)d_in[10];
    const float* W_out  = (const float*)d_in[11];
    float* out = (float*)d_out;

    __nv_bfloat16 *p_xnb, *p_xz, *p_yp, *p_Wt, *p_WoT;
    cudaGetSymbolAddress((void**)&p_xnb, g_xnb);
    cudaGetSymbolAddress((void**)&p_xz,  g_xz);
    cudaGetSymbolAddress((void**)&p_yp,  g_yp);
    cudaGetSymbolAddress((void**)&p_Wt,  g_Wt);
    cudaGetSymbolAddress((void**)&p_WoT, g_WoT);

    const int SMEM = 3 * (128 + 64) * 64 * 2;   // 73728
    cudaFuncSetAttribute(hmma_gemm<CDIM,false>,
                         cudaFuncAttributeMaxDynamicSharedMemorySize, SMEM);
    cudaFuncSetAttribute(hmma_gemm<DI,true>,
                         cudaFuncAttributeMaxDynamicSharedMemorySize, SMEM);

    // 0. weight transposes -> bf16 K-major (merged)
    wtrans_kernel<<<(NXZ*CDIM + CDIM*DI + 255)/256, 256>>>(W_in, W_out);

    // 1. LayerNorm -> bf16
    ln_kernel<<<NTOK/8, 256>>>(x, ln_w, ln_b);

    // 2. xz = xn @ W_in  (HMMA bf16): [NTOK,192] x [192,768] -> bf16
    {
        dim3 grid(NXZ/64, NTOK/128);
        hmma_gemm<CDIM,false><<<grid, 256, SMEM>>>(p_xnb, p_Wt, nullptr, nullptr, p_xz, NXZ);
    }

    // 3. fused conv+silu + proj + dt + {dA,dBu}
    proj_dt_kernel<<<NTOK/8, 256>>>(W_xprj, W_dt, b_dt, A_log, conv_w, conv_b);

    // 4-6. chunked selective scan
    scan1_kernel<<<(NB*NC*DI)/256, 256>>>();
    scan2_kernel<<<(NB*DI)/256, 256>>>();
    scan3_kernel<<<(NB*NC*DI)/256, 256>>>(Dw);

    // 7. out = yp @ W_out + x  (HMMA bf16): [NTOK,384] x [384,192] -> fp32 + resid
    {
        dim3 grid(CDIM/64, NTOK/128);
        hmma_gemm<DI,true><<<grid, 256, SMEM>>>(p_yp, p_WoT, x, out, nullptr, CDIM);
    }
}

// round 7
// speedup vs baseline: 2.1430x; 1.1299x over previous
#include <cuda_runtime.h>
#include <cuda_bf16.h>
#include <cstdint>
#include <cstddef>

// Problem constants
#define NB   16
#define LSEQ 9216
#define NTOK 147456          // NB*LSEQ
#define CDIM 192
#define DI   384             // d_inner
#define NXZ  768             // 2*DI
#define DTR  12              // dt_rank
#define NPROJ 14             // dt_rank + 2*d_state
#define NPP  16              // padded proj cols
#define NC   36              // scan chunks per sequence
#define CL   256             // chunk length (NC*CL = LSEQ)

// -------- scratch (device globals; no allocation allowed) --------
__device__ __nv_bfloat16  g_xnb[(size_t)NTOK * CDIM];  // layernorm output (bf16)
__device__ __nv_bfloat16  g_xz [(size_t)NTOK * NXZ];   // cols [0,384)=xb, [384,768)=z
__device__ __nv_bfloat16  g_u  [(size_t)NTOK * DI];    // silu(conv(xb))
__device__ __nv_bfloat162 g_ad [(size_t)NTOK * DI];    // {dA, dBu} per (t,i)
__device__ __nv_bfloat16  g_yp [(size_t)NTOK * DI];    // gated scan output
__device__ float          g_pr [(size_t)NTOK * NPP];   // proj output (fp32)
__device__ __nv_bfloat16  g_Wt [NXZ * CDIM];           // W_in^T  [768,192] K-major
__device__ __nv_bfloat16  g_WoT[CDIM * DI];            // W_out^T [192,384] K-major
__device__ __nv_bfloat16  g_WxT[NPP * DI];             // W_xproj^T padded [16,384] K-major
__device__ float g_Cv[NTOK];
__device__ float g_ca[NB * NC * DI];
__device__ float g_ch[NB * NC * DI];
__device__ float g_hi[NB * NC * DI];

__device__ __forceinline__ float sigmoidf_(float v) { return 1.0f / (1.0f + expf(-v)); }
__device__ __forceinline__ float siluf_(float v)    { return v * sigmoidf_(v); }
__device__ __forceinline__ float softplusf_(float v){ return v > 20.0f ? v : log1pf(expf(v)); }

__device__ __forceinline__ uint32_t smem_u32(const void* p) {
    uint32_t a;
    asm("{ .reg .u64 t; cvta.to.shared.u64 t, %1; cvt.u32.u64 %0, t; }" : "=r"(a) : "l"(p));
    return a;
}
__device__ __forceinline__ void ldsm_x4(uint32_t addr, uint32_t& r0, uint32_t& r1,
                                        uint32_t& r2, uint32_t& r3) {
    asm volatile("ldmatrix.sync.aligned.m8n8.x4.shared.b16 {%0,%1,%2,%3}, [%4];"
                 : "=r"(r0), "=r"(r1), "=r"(r2), "=r"(r3) : "r"(addr));
}
__device__ __forceinline__ void mma_bf16(float* c, const uint32_t* a, uint32_t b0, uint32_t b1) {
    asm volatile("mma.sync.aligned.m16n8k16.row.col.f32.bf16.bf16.f32 "
                 "{%0,%1,%2,%3}, {%4,%5,%6,%7}, {%8,%9}, {%0,%1,%2,%3};"
                 : "+f"(c[0]), "+f"(c[1]), "+f"(c[2]), "+f"(c[3])
                 : "r"(a[0]), "r"(a[1]), "r"(a[2]), "r"(a[3]), "r"(b0), "r"(b1));
}
__device__ __forceinline__ void cp16(uint32_t s, const void* g) {
    asm volatile("cp.async.cg.shared.global [%0], [%1], 16;" :: "r"(s), "l"(g));
}
__device__ __forceinline__ void wait_groups(int n) {
    if (n == 0)      asm volatile("cp.async.wait_group 0;");
    else if (n == 1) asm volatile("cp.async.wait_group 1;");
}

// ================= weight transposes (tiny, merged) =================
__global__ void wtrans_kernel(const float* __restrict__ W_in,
                              const float* __restrict__ W_out,
                              const float* __restrict__ Wx) {
    int i = blockIdx.x * 256 + threadIdx.x;
    if (i < NXZ * CDIM) {
        int n = i / CDIM, k = i % CDIM;
        g_Wt[i] = __float2bfloat16_rn(W_in[(size_t)k * NXZ + n]);
    }
    int j = i - NXZ * CDIM;
    if (j >= 0 && j < CDIM * DI) {
        int n = j / DI, k = j % DI;
        g_WoT[j] = __float2bfloat16_rn(W_out[(size_t)k * CDIM + n]);
    }
    int q = j - CDIM * DI;
    if (q >= 0 && q < NPP * DI) {
        int n = q / DI, k = q % DI;     // n = padded proj col, k = inner dim
        g_WxT[q] = (n < NPROJ) ? __float2bfloat16_rn(Wx[(size_t)k * NPROJ + n])
                               : __float2bfloat16_rn(0.f);
    }
}

// ================= LayerNorm -> bf16 =================
__global__ void ln_kernel(const float* __restrict__ x,
                          const float* __restrict__ w,
                          const float* __restrict__ b)
{
    int warp = threadIdx.x >> 5, lane = threadIdx.x & 31;
    size_t t = (size_t)blockIdx.x * 8 + warp;
    const float* row = x + t * CDIM;
    float v[6];
    float s = 0.f;
#pragma unroll
    for (int r = 0; r < 6; r++) { v[r] = row[lane + 32*r]; s += v[r]; }
#pragma unroll
    for (int o = 16; o; o >>= 1) s += __shfl_xor_sync(0xffffffffu, s, o);
    float mu = s * (1.0f/192.0f);
    float q = 0.f;
#pragma unroll
    for (int r = 0; r < 6; r++) { float d = v[r] - mu; q += d*d; }
#pragma unroll
    for (int o = 16; o; o >>= 1) q += __shfl_xor_sync(0xffffffffu, q, o);
    float inv = rsqrtf(q * (1.0f/192.0f) + 1e-5f);
    __nv_bfloat16* out = g_xnb + t * CDIM;
#pragma unroll
    for (int r = 0; r < 6; r++) {
        int c = lane + 32*r;
        out[c] = __float2bfloat16_rn((v[r] - mu) * inv * w[c] + b[c]);
    }
}

// ================= pipelined HMMA bf16 GEMM (3-stage ring, 1 sync/iter) =====
// C[M,N] = A[M,K](bf16 K-major) @ Bw[N,K](bf16 K-major)^T.
// BM=128, BN=64, BK=64, 256 threads, 8 warps (4x2), warp tile 32x32.
template<int K, bool RESID>
__global__ __launch_bounds__(256, 3)
void hmma_gemm(const __nv_bfloat16* __restrict__ A,
               const __nv_bfloat16* __restrict__ Bw,
               const float* __restrict__ resid,
               float* __restrict__ outf,
               __nv_bfloat16* __restrict__ outb,
               int N)
{
    constexpr int BM = 128, BN = 64, BK = 64;
    constexpr int KC = K / BK;
    constexpr int RING = 3;
    constexpr int ABYTES = BM * BK * 2;              // 16384
    constexpr int STAGE  = (BM + BN) * BK * 2;       // 24576
    extern __shared__ char smem[];
    int tid = threadIdx.x, wid = tid >> 5, lane = tid & 31;
    size_t bm = (size_t)blockIdx.y * BM;
    int bn = blockIdx.x * BN;
    int m0 = (wid & 3) * 32, n0 = (wid >> 2) * 32;

    uint32_t smem_base = smem_u32(smem);

    int arow[4], ach[4];
#pragma unroll
    for (int it = 0; it < 4; it++) {
        int c = tid + it * 256;
        arow[it] = c >> 3; ach[it] = c & 7;
    }
    int brow[2], bch[2];
#pragma unroll
    for (int it = 0; it < 2; it++) {
        int c = tid + it * 256;
        brow[it] = c >> 3; bch[it] = c & 7;
    }

    auto load_stage = [&](int st, int k0) {
        uint32_t sbase = smem_base + st * STAGE;
#pragma unroll
        for (int it = 0; it < 4; it++) {
            int row = arow[it], ch = ach[it];
            cp16(sbase + (uint32_t)(((row << 3) + (ch ^ (row & 7))) * 16),
                 A + (bm + row) * K + k0 + ch * 8);
        }
#pragma unroll
        for (int it = 0; it < 2; it++) {
            int row = brow[it], ch = bch[it];
            cp16(sbase + ABYTES + (uint32_t)(((row << 3) + (ch ^ (row & 7))) * 16),
                 Bw + (size_t)(bn + row) * K + k0 + ch * 8);
        }
        asm volatile("cp.async.commit_group;");
    };

    float acc[2][4][4];
#pragma unroll
    for (int ti = 0; ti < 2; ti++)
#pragma unroll
        for (int j = 0; j < 4; j++)
#pragma unroll
            for (int e = 0; e < 4; e++) acc[ti][j][e] = 0.f;

    int a_r[2], b_r[4];
#pragma unroll
    for (int ti = 0; ti < 2; ti++) a_r[ti] = m0 + 16 * ti + (lane & 15);
#pragma unroll
    for (int j = 0; j < 4; j++)    b_r[j]  = n0 + 8 * j + (lane & 7);
    int a_klo = lane >> 4;
    int b_klo = lane >> 3;

    load_stage(0, 0);
    load_stage(1, BK);

#pragma unroll
    for (int kc = 0; kc < KC; kc++) {
        wait_groups(kc >= KC - 1 ? 0 : 1);
        __syncthreads();
        if (kc + 2 < KC) load_stage((kc + 2) % RING, (kc + 2) * BK);

        uint32_t sa = smem_base + (kc % RING) * STAGE;
        uint32_t sb = sa + ABYTES;
#pragma unroll
        for (int kb2 = 0; kb2 < 2; kb2++) {
            uint32_t br[4][4];
#pragma unroll
            for (int j = 0; j < 4; j++) {
                int r = b_r[j];
                uint32_t addr = sb + (uint32_t)(((r << 3) + ((kb2 * 4 + b_klo) ^ (r & 7))) * 16);
                ldsm_x4(addr, br[j][0], br[j][1], br[j][2], br[j][3]);
            }
#pragma unroll
            for (int ks2 = 0; ks2 < 2; ks2++) {
                uint32_t ar[2][4];
#pragma unroll
                for (int ti = 0; ti < 2; ti++) {
                    int r = a_r[ti];
                    uint32_t addr = sa + (uint32_t)(((r << 3) +
                        ((kb2 * 4 + ks2 * 2 + a_klo) ^ (r & 7))) * 16);
                    ldsm_x4(addr, ar[ti][0], ar[ti][1], ar[ti][2], ar[ti][3]);
                }
#pragma unroll
                for (int ti = 0; ti < 2; ti++)
#pragma unroll
                    for (int j = 0; j < 4; j++)
                        mma_bf16(acc[ti][j], ar[ti], br[j][2 * ks2], br[j][2 * ks2 + 1]);
            }
        }
    }

#pragma unroll
    for (int ti = 0; ti < 2; ti++)
#pragma unroll
        for (int j = 0; j < 4; j++) {
            int row = m0 + 16 * ti + (lane >> 2);
            int col = bn + n0 + 8 * j + (lane & 3) * 2;
#pragma unroll
            for (int half = 0; half < 2; half++) {
                size_t off = (bm + row + 8 * half) * (size_t)N + col;
                float v0 = acc[ti][j][2 * half], v1 = acc[ti][j][2 * half + 1];
                if (RESID) {
                    float2 rv = *(const float2*)(resid + off);
                    *(float2*)(outf + off) = make_float2(v0 + rv.x, v1 + rv.y);
                } else {
                    __nv_bfloat162 p;
                    p.x = __float2bfloat16_rn(v0);
                    p.y = __float2bfloat16_rn(v1);
                    *(__nv_bfloat162*)(outb + off) = p;
                }
            }
        }
}

// ============ proj GEMM: g_pr[NTOK,16] = u[NTOK,384] @ WxT^T ============
// BM=128, BN=16, BK=64, 8 warps each 16 rows x 16 cols, 3-stage ring.
__global__ __launch_bounds__(256, 3)
void proj_gemm()
{
    constexpr int BM = 128, BK = 64, K = DI, KC = K / BK, RING = 3;
    constexpr int ABYTES = BM * BK * 2;              // 16384
    constexpr int STAGE  = ABYTES + NPP * BK * 2;    // 18432
    extern __shared__ char smem[];
    const __nv_bfloat16* A = g_u;
    int tid = threadIdx.x, wid = tid >> 5, lane = tid & 31;
    size_t bm = (size_t)blockIdx.x * BM;
    int m0 = wid * 16;

    uint32_t smem_base = smem_u32(smem);

    int arow[4], ach[4];
#pragma unroll
    for (int it = 0; it < 4; it++) {
        int c = tid + it * 256;
        arow[it] = c >> 3; ach[it] = c & 7;
    }
    int brow = tid >> 3, bch = tid & 7;   // tid<128 loads B

    auto load_stage = [&](int st, int k0) {
        uint32_t sbase = smem_base + st * STAGE;
#pragma unroll
        for (int it = 0; it < 4; it++) {
            int row = arow[it], ch = ach[it];
            cp16(sbase + (uint32_t)(((row << 3) + (ch ^ (row & 7))) * 16),
                 A + (bm + row) * K + k0 + ch * 8);
        }
        if (tid < NPP * 8) {
            cp16(sbase + ABYTES + (uint32_t)(((brow << 3) + (bch ^ (brow & 7))) * 16),
                 g_WxT + (size_t)brow * K + k0 + bch * 8);
        }
        asm volatile("cp.async.commit_group;");
    };

    float acc[2][4];
#pragma unroll
    for (int j = 0; j < 2; j++)
#pragma unroll
        for (int e = 0; e < 4; e++) acc[j][e] = 0.f;

    int a_r = m0 + (lane & 15);
    int b_r[2];
#pragma unroll
    for (int j = 0; j < 2; j++) b_r[j] = 8 * j + (lane & 7);
    int a_klo = lane >> 4;
    int b_klo = lane >> 3;

    load_stage(0, 0);
    load_stage(1, BK);

#pragma unroll
    for (int kc = 0; kc < KC; kc++) {
        wait_groups(kc >= KC - 1 ? 0 : 1);
        __syncthreads();
        if (kc + 2 < KC) load_stage((kc + 2) % RING, (kc + 2) * BK);

        uint32_t sa = smem_base + (kc % RING) * STAGE;
        uint32_t sb = sa + ABYTES;
#pragma unroll
        for (int kb2 = 0; kb2 < 2; kb2++) {
            uint32_t br[2][4];
#pragma unroll
            for (int j = 0; j < 2; j++) {
                int r = b_r[j];
                uint32_t addr = sb + (uint32_t)(((r << 3) + ((kb2 * 4 + b_klo) ^ (r & 7))) * 16);
                ldsm_x4(addr, br[j][0], br[j][1], br[j][2], br[j][3]);
            }
#pragma unroll
            for (int ks2 = 0; ks2 < 2; ks2++) {
                uint32_t ar[4];
                {
                    int r = a_r;
                    uint32_t addr = sa + (uint32_t)(((r << 3) +
                        ((kb2 * 4 + ks2 * 2 + a_klo) ^ (r & 7))) * 16);
                    ldsm_x4(addr, ar[0], ar[1], ar[2], ar[3]);
                }
#pragma unroll
                for (int j = 0; j < 2; j++)
                    mma_bf16(acc[j], ar, br[j][2 * ks2], br[j][2 * ks2 + 1]);
            }
        }
    }

#pragma unroll
    for (int j = 0; j < 2; j++) {
        int row = m0 + (lane >> 2);
        int col = 8 * j + (lane & 3) * 2;
#pragma unroll
        for (int half = 0; half < 2; half++) {
            size_t off = (bm + row + 8 * half) * (size_t)NPP + col;
            *(float2*)(g_pr + off) = make_float2(acc[j][2 * half], acc[j][2 * half + 1]);
        }
    }
}

// ================= depthwise causal conv k=3 + SiLU =================
__global__ void conv_silu_kernel(const float* __restrict__ cw, const float* __restrict__ cb)
{
    size_t idx = (size_t)blockIdx.x * 256 + threadIdx.x;   // over NTOK*DI
    int i = (int)(idx % DI);
    size_t t = idx / DI;
    int l = (int)(t % LSEQ);
    const __nv_bfloat16* base = g_xz + t * NXZ + i;        // xb = cols [0,384)
    float acc = cb[i];
    float w0 = cw[i*3+0], w1 = cw[i*3+1], w2 = cw[i*3+2];
    if (l >= 2) acc = fmaf(__bfloat162float(base[-2*NXZ]), w0, acc);
    if (l >= 1) acc = fmaf(__bfloat162float(base[-1*NXZ]), w1, acc);
    acc = fmaf(__bfloat162float(base[0]), w2, acc);
    g_u[idx] = __float2bfloat16_rn(siluf_(acc));
}

// ========== dt + dA + dBu streaming kernel: block per token, 384 thr ==========
__global__ __launch_bounds__(384)
void dt_ad_kernel(const float* __restrict__ Wdt, const float* __restrict__ bdt,
                  const float* __restrict__ A_log)
{
    __shared__ float spr[NPP];
    size_t t = blockIdx.x;
    int i = threadIdx.x;
    if (i < NPP) spr[i] = g_pr[t * NPP + i];
    __syncthreads();

    float s = bdt[i];
#pragma unroll
    for (int k = 0; k < DTR; k++) s = fmaf(spr[k], Wdt[k * DI + i], s);
    float dt = softplusf_(s);
    float dA = expf(dt * (-expf(A_log[i])));
    float uu = __bfloat162float(g_u[t * DI + i]);
    float dbu = dt * spr[DTR] * uu;
    __nv_bfloat162 p;
    p.x = __float2bfloat16_rn(dA);
    p.y = __float2bfloat16_rn(dbu);
    g_ad[t * DI + i] = p;
    if (i == 0) g_Cv[t] = spr[DTR + 1];
}

// ================= chunked selective scan (pure FMA streaming) =================
__global__ void scan1_kernel()
{
    int idx = blockIdx.x * 256 + threadIdx.x;   // (b*NC + c)*DI + i
    int i = idx % DI;
    int c = (idx / DI) % NC;
    int b = idx / (DI * NC);
    size_t t0 = (size_t)b * LSEQ + (size_t)c * CL;
    float h = 0.f, ap = 1.f;
#pragma unroll 4
    for (int s = 0; s < CL; s++) {
        __nv_bfloat162 p = g_ad[(t0 + s) * DI + i];
        float dA = __bfloat162float(p.x);
        h = fmaf(dA, h, __bfloat162float(p.y));
        ap *= dA;
    }
    g_ca[idx] = ap; g_ch[idx] = h;
}

__global__ void scan2_kernel()
{
    int idx = blockIdx.x * 256 + threadIdx.x;   // b*DI + i
    int i = idx % DI;
    int b = idx / DI;
    float h = 0.f;
    for (int c = 0; c < NC; c++) {
        int j = (b * NC + c) * DI + i;
        g_hi[j] = h;
        h = fmaf(g_ca[j], h, g_ch[j]);
    }
}

__global__ void scan3_kernel(const float* __restrict__ Dw)
{
    int idx = blockIdx.x * 256 + threadIdx.x;
    int i = idx % DI;
    int c = (idx / DI) % NC;
    int b = idx / (DI * NC);
    float Dv = Dw[i];
    size_t t0 = (size_t)b * LSEQ + (size_t)c * CL;
    float h = g_hi[idx];
#pragma unroll 4
    for (int s = 0; s < CL; s++) {
        size_t t = t0 + s;
        __nv_bfloat162 p = g_ad[t * DI + i];
        h = fmaf(__bfloat162float(p.x), h, __bfloat162float(p.y));
        float uu = __bfloat162float(g_u[t * DI + i]);
        float y = fmaf(h, g_Cv[t], uu * Dv);
        float z = __bfloat162float(g_xz[t * NXZ + DI + i]);
        g_yp[t * DI + i] = __float2bfloat16_rn(y * siluf_(z));
    }
}

extern "C" void kernel_launch(void* const* d_in, const int* in_sizes, int n_in,
                              void* d_out, int out_size)
{
    const float* x      = (const float*)d_in[0];
    const float* ln_w   = (const float*)d_in[1];
    const float* ln_b   = (const float*)d_in[2];
    const float* W_in   = (const float*)d_in[3];
    const float* conv_w = (const float*)d_in[4];
    const float* conv_b = (const float*)d_in[5];
    const float* W_xprj = (const float*)d_in[6];
    const float* W_dt   = (const float*)d_in[7];
    const float* b_dt   = (const float*)d_in[8];
    const float* A_log  = (const float*)d_in[9];
    const float* Dw     = (const float*)d_in[10];
    const float* W_out  = (const float*)d_in[11];
    float* out = (float*)d_out;

    __nv_bfloat16 *p_xnb, *p_xz, *p_yp, *p_Wt, *p_WoT;
    cudaGetSymbolAddress((void**)&p_xnb, g_xnb);
    cudaGetSymbolAddress((void**)&p_xz,  g_xz);
    cudaGetSymbolAddress((void**)&p_yp,  g_yp);
    cudaGetSymbolAddress((void**)&p_Wt,  g_Wt);
    cudaGetSymbolAddress((void**)&p_WoT, g_WoT);

    const int SMEM  = 3 * (128 + 64) * 64 * 2;   // 73728
    const int SMEMP = 3 * (128 + 16) * 64 * 2;   // 55296
    cudaFuncSetAttribute(hmma_gemm<CDIM,false>,
                         cudaFuncAttributeMaxDynamicSharedMemorySize, SMEM);
    cudaFuncSetAttribute(hmma_gemm<DI,true>,
                         cudaFuncAttributeMaxDynamicSharedMemorySize, SMEM);
    cudaFuncSetAttribute(proj_gemm,
                         cudaFuncAttributeMaxDynamicSharedMemorySize, SMEMP);

    // 0. weight transposes -> bf16 K-major (merged)
    wtrans_kernel<<<(NXZ*CDIM + CDIM*DI + NPP*DI + 255)/256, 256>>>(W_in, W_out, W_xprj);

    // 1. LayerNorm -> bf16
    ln_kernel<<<NTOK/8, 256>>>(x, ln_w, ln_b);

    // 2. xz = xn @ W_in  (HMMA bf16): [NTOK,192] x [192,768] -> bf16
    {
        dim3 grid(NXZ/64, NTOK/128);
        hmma_gemm<CDIM,false><<<grid, 256, SMEM>>>(p_xnb, p_Wt, nullptr, nullptr, p_xz, NXZ);
    }

    // 3. u = silu(causal depthwise conv(xb))
    conv_silu_kernel<<<(NTOK*(size_t)DI)/256, 256>>>(conv_w, conv_b);

    // 4. proj GEMM: g_pr = u @ WxPad (HMMA)
    proj_gemm<<<NTOK/128, 256, SMEMP>>>();

    // 5. dt + dA + dBu streaming
    dt_ad_kernel<<<NTOK, 384>>>(W_dt, b_dt, A_log);

    // 6-8. chunked selective scan
    scan1_kernel<<<(NB*NC*DI)/256, 256>>>();
    scan2_kernel<<<(NB*DI)/256, 256>>>();
    scan3_kernel<<<(NB*NC*DI)/256, 256>>>(Dw);

    // 9. out = yp @ W_out + x  (HMMA bf16): [NTOK,384] x [384,192] -> fp32 + resid
    {
        dim3 grid(CDIM/64, NTOK/128);
        hmma_gemm<DI,true><<<grid, 256, SMEM>>>(p_yp, p_WoT, x, out, nullptr, CDIM);
    }
}

// round 8
// speedup vs baseline: 2.4242x; 1.1312x over previous
#include <cuda_runtime.h>
#include <cuda_bf16.h>
#include <cstdint>
#include <cstddef>

// Problem constants
#define NB   16
#define LSEQ 9216
#define NTOK 147456          // NB*LSEQ
#define CDIM 192
#define DI   384             // d_inner
#define NXZ  768             // 2*DI
#define DTR  12              // dt_rank
#define NPROJ 14             // dt_rank + 2*d_state
#define NPP  16              // padded proj cols
#define NC   36              // scan chunks per sequence
#define CL   256             // chunk length (NC*CL = LSEQ)

// -------- scratch (device globals; no allocation allowed) --------
__device__ __nv_bfloat16  g_xnb[(size_t)NTOK * CDIM];  // layernorm output (bf16)
__device__ __nv_bfloat16  g_xz [(size_t)NTOK * NXZ];   // cols [0,384)=xb, [384,768)=z
__device__ __nv_bfloat16  g_u  [(size_t)NTOK * DI];    // silu(conv(xb))
__device__ __nv_bfloat162 g_ad [(size_t)NTOK * DI];    // {dA, dBu} per (t,i)
__device__ __nv_bfloat16  g_yp [(size_t)NTOK * DI];    // gated scan output
__device__ float          g_pr [(size_t)NTOK * NPP];   // proj output (fp32)
__device__ __nv_bfloat16  g_Wt [NXZ * CDIM];           // W_in^T  [768,192] K-major
__device__ __nv_bfloat16  g_WoT[CDIM * DI];            // W_out^T [192,384] K-major
__device__ __nv_bfloat16  g_WxT[NPP * DI];             // W_xproj^T padded [16,384] K-major
__device__ float g_Cv[NTOK];
__device__ float g_ca[NB * NC * DI];
__device__ float g_ch[NB * NC * DI];
__device__ float g_hi[NB * NC * DI];

__device__ __forceinline__ float sigmoidf_(float v) { return 1.0f / (1.0f + expf(-v)); }
__device__ __forceinline__ float siluf_(float v)    { return v * sigmoidf_(v); }
__device__ __forceinline__ float softplusf_(float v){ return v > 20.0f ? v : log1pf(expf(v)); }

__device__ __forceinline__ uint32_t smem_u32(const void* p) {
    uint32_t a;
    asm("{ .reg .u64 t; cvta.to.shared.u64 t, %1; cvt.u32.u64 %0, t; }" : "=r"(a) : "l"(p));
    return a;
}
__device__ __forceinline__ void ldsm_x4(uint32_t addr, uint32_t& r0, uint32_t& r1,
                                        uint32_t& r2, uint32_t& r3) {
    asm volatile("ldmatrix.sync.aligned.m8n8.x4.shared.b16 {%0,%1,%2,%3}, [%4];"
                 : "=r"(r0), "=r"(r1), "=r"(r2), "=r"(r3) : "r"(addr));
}
__device__ __forceinline__ void mma_bf16(float* c, const uint32_t* a, uint32_t b0, uint32_t b1) {
    asm volatile("mma.sync.aligned.m16n8k16.row.col.f32.bf16.bf16.f32 "
                 "{%0,%1,%2,%3}, {%4,%5,%6,%7}, {%8,%9}, {%0,%1,%2,%3};"
                 : "+f"(c[0]), "+f"(c[1]), "+f"(c[2]), "+f"(c[3])
                 : "r"(a[0]), "r"(a[1]), "r"(a[2]), "r"(a[3]), "r"(b0), "r"(b1));
}
__device__ __forceinline__ void cp16(uint32_t s, const void* g) {
    asm volatile("cp.async.cg.shared.global [%0], [%1], 16;" :: "r"(s), "l"(g));
}
__device__ __forceinline__ void wait_groups(int n) {
    if (n == 0)      asm volatile("cp.async.wait_group 0;");
    else if (n == 1) asm volatile("cp.async.wait_group 1;");
}

// ================= weight transposes (tiny, merged) =================
__global__ void wtrans_kernel(const float* __restrict__ W_in,
                              const float* __restrict__ W_out,
                              const float* __restrict__ Wx) {
    int i = blockIdx.x * 256 + threadIdx.x;
    if (i < NXZ * CDIM) {
        int n = i / CDIM, k = i % CDIM;
        g_Wt[i] = __float2bfloat16_rn(W_in[(size_t)k * NXZ + n]);
    }
    int j = i - NXZ * CDIM;
    if (j >= 0 && j < CDIM * DI) {
        int n = j / DI, k = j % DI;
        g_WoT[j] = __float2bfloat16_rn(W_out[(size_t)k * CDIM + n]);
    }
    int q = j - CDIM * DI;
    if (q >= 0 && q < NPP * DI) {
        int n = q / DI, k = q % DI;
        g_WxT[q] = (n < NPROJ) ? __float2bfloat16_rn(Wx[(size_t)k * NPROJ + n])
                               : __float2bfloat16_rn(0.f);
    }
}

// ================= LayerNorm -> bf16 =================
__global__ void ln_kernel(const float* __restrict__ x,
                          const float* __restrict__ w,
                          const float* __restrict__ b)
{
    int warp = threadIdx.x >> 5, lane = threadIdx.x & 31;
    size_t t = (size_t)blockIdx.x * 8 + warp;
    const float* row = x + t * CDIM;
    float v[6];
    float s = 0.f;
#pragma unroll
    for (int r = 0; r < 6; r++) { v[r] = row[lane + 32*r]; s += v[r]; }
#pragma unroll
    for (int o = 16; o; o >>= 1) s += __shfl_xor_sync(0xffffffffu, s, o);
    float mu = s * (1.0f/192.0f);
    float q = 0.f;
#pragma unroll
    for (int r = 0; r < 6; r++) { float d = v[r] - mu; q += d*d; }
#pragma unroll
    for (int o = 16; o; o >>= 1) q += __shfl_xor_sync(0xffffffffu, q, o);
    float inv = rsqrtf(q * (1.0f/192.0f) + 1e-5f);
    __nv_bfloat16* out = g_xnb + t * CDIM;
#pragma unroll
    for (int r = 0; r < 6; r++) {
        int c = lane + 32*r;
        out[c] = __float2bfloat16_rn((v[r] - mu) * inv * w[c] + b[c]);
    }
}

// ================= pipelined HMMA bf16 GEMM (3-stage ring, 1 sync/iter) =====
template<int K, bool RESID>
__global__ __launch_bounds__(256, 3)
void hmma_gemm(const __nv_bfloat16* __restrict__ A,
               const __nv_bfloat16* __restrict__ Bw,
               const float* __restrict__ resid,
               float* __restrict__ outf,
               __nv_bfloat16* __restrict__ outb,
               int N)
{
    constexpr int BM = 128, BN = 64, BK = 64;
    constexpr int KC = K / BK;
    constexpr int RING = 3;
    constexpr int ABYTES = BM * BK * 2;
    constexpr int STAGE  = (BM + BN) * BK * 2;
    extern __shared__ char smem[];
    int tid = threadIdx.x, wid = tid >> 5, lane = tid & 31;
    size_t bm = (size_t)blockIdx.y * BM;
    int bn = blockIdx.x * BN;
    int m0 = (wid & 3) * 32, n0 = (wid >> 2) * 32;

    uint32_t smem_base = smem_u32(smem);

    int arow[4], ach[4];
#pragma unroll
    for (int it = 0; it < 4; it++) {
        int c = tid + it * 256;
        arow[it] = c >> 3; ach[it] = c & 7;
    }
    int brow[2], bch[2];
#pragma unroll
    for (int it = 0; it < 2; it++) {
        int c = tid + it * 256;
        brow[it] = c >> 3; bch[it] = c & 7;
    }

    auto load_stage = [&](int st, int k0) {
        uint32_t sbase = smem_base + st * STAGE;
#pragma unroll
        for (int it = 0; it < 4; it++) {
            int row = arow[it], ch = ach[it];
            cp16(sbase + (uint32_t)(((row << 3) + (ch ^ (row & 7))) * 16),
                 A + (bm + row) * K + k0 + ch * 8);
        }
#pragma unroll
        for (int it = 0; it < 2; it++) {
            int row = brow[it], ch = bch[it];
            cp16(sbase + ABYTES + (uint32_t)(((row << 3) + (ch ^ (row & 7))) * 16),
                 Bw + (size_t)(bn + row) * K + k0 + ch * 8);
        }
        asm volatile("cp.async.commit_group;");
    };

    float acc[2][4][4];
#pragma unroll
    for (int ti = 0; ti < 2; ti++)
#pragma unroll
        for (int j = 0; j < 4; j++)
#pragma unroll
            for (int e = 0; e < 4; e++) acc[ti][j][e] = 0.f;

    int a_r[2], b_r[4];
#pragma unroll
    for (int ti = 0; ti < 2; ti++) a_r[ti] = m0 + 16 * ti + (lane & 15);
#pragma unroll
    for (int j = 0; j < 4; j++)    b_r[j]  = n0 + 8 * j + (lane & 7);
    int a_klo = lane >> 4;
    int b_klo = lane >> 3;

    load_stage(0, 0);
    load_stage(1, BK);

#pragma unroll
    for (int kc = 0; kc < KC; kc++) {
        wait_groups(kc >= KC - 1 ? 0 : 1);
        __syncthreads();
        if (kc + 2 < KC) load_stage((kc + 2) % RING, (kc + 2) * BK);

        uint32_t sa = smem_base + (kc % RING) * STAGE;
        uint32_t sb = sa + ABYTES;
#pragma unroll
        for (int kb2 = 0; kb2 < 2; kb2++) {
            uint32_t br[4][4];
#pragma unroll
            for (int j = 0; j < 4; j++) {
                int r = b_r[j];
                uint32_t addr = sb + (uint32_t)(((r << 3) + ((kb2 * 4 + b_klo) ^ (r & 7))) * 16);
                ldsm_x4(addr, br[j][0], br[j][1], br[j][2], br[j][3]);
            }
#pragma unroll
            for (int ks2 = 0; ks2 < 2; ks2++) {
                uint32_t ar[2][4];
#pragma unroll
                for (int ti = 0; ti < 2; ti++) {
                    int r = a_r[ti];
                    uint32_t addr = sa + (uint32_t)(((r << 3) +
                        ((kb2 * 4 + ks2 * 2 + a_klo) ^ (r & 7))) * 16);
                    ldsm_x4(addr, ar[ti][0], ar[ti][1], ar[ti][2], ar[ti][3]);
                }
#pragma unroll
                for (int ti = 0; ti < 2; ti++)
#pragma unroll
                    for (int j = 0; j < 4; j++)
                        mma_bf16(acc[ti][j], ar[ti], br[j][2 * ks2], br[j][2 * ks2 + 1]);
            }
        }
    }

#pragma unroll
    for (int ti = 0; ti < 2; ti++)
#pragma unroll
        for (int j = 0; j < 4; j++) {
            int row = m0 + 16 * ti + (lane >> 2);
            int col = bn + n0 + 8 * j + (lane & 3) * 2;
#pragma unroll
            for (int half = 0; half < 2; half++) {
                size_t off = (bm + row + 8 * half) * (size_t)N + col;
                float v0 = acc[ti][j][2 * half], v1 = acc[ti][j][2 * half + 1];
                if (RESID) {
                    float2 rv = *(const float2*)(resid + off);
                    *(float2*)(outf + off) = make_float2(v0 + rv.x, v1 + rv.y);
                } else {
                    __nv_bfloat162 p;
                    p.x = __float2bfloat16_rn(v0);
                    p.y = __float2bfloat16_rn(v1);
                    *(__nv_bfloat162*)(outb + off) = p;
                }
            }
        }
}

// ============ proj GEMM: g_pr[NTOK,16] = u[NTOK,384] @ WxT^T ============
__global__ __launch_bounds__(256, 3)
void proj_gemm()
{
    constexpr int BM = 128, BK = 64, K = DI, KC = K / BK, RING = 3;
    constexpr int ABYTES = BM * BK * 2;
    constexpr int STAGE  = ABYTES + NPP * BK * 2;
    extern __shared__ char smem[];
    const __nv_bfloat16* A = g_u;
    int tid = threadIdx.x, wid = tid >> 5, lane = tid & 31;
    size_t bm = (size_t)blockIdx.x * BM;
    int m0 = wid * 16;

    uint32_t smem_base = smem_u32(smem);

    int arow[4], ach[4];
#pragma unroll
    for (int it = 0; it < 4; it++) {
        int c = tid + it * 256;
        arow[it] = c >> 3; ach[it] = c & 7;
    }
    int brow = tid >> 3, bch = tid & 7;

    auto load_stage = [&](int st, int k0) {
        uint32_t sbase = smem_base + st * STAGE;
#pragma unroll
        for (int it = 0; it < 4; it++) {
            int row = arow[it], ch = ach[it];
            cp16(sbase + (uint32_t)(((row << 3) + (ch ^ (row & 7))) * 16),
                 A + (bm + row) * K + k0 + ch * 8);
        }
        if (tid < NPP * 8) {
            cp16(sbase + ABYTES + (uint32_t)(((brow << 3) + (bch ^ (brow & 7))) * 16),
                 g_WxT + (size_t)brow * K + k0 + bch * 8);
        }
        asm volatile("cp.async.commit_group;");
    };

    float acc[2][4];
#pragma unroll
    for (int j = 0; j < 2; j++)
#pragma unroll
        for (int e = 0; e < 4; e++) acc[j][e] = 0.f;

    int a_r = m0 + (lane & 15);
    int b_r[2];
#pragma unroll
    for (int j = 0; j < 2; j++) b_r[j] = 8 * j + (lane & 7);
    int a_klo = lane >> 4;
    int b_klo = lane >> 3;

    load_stage(0, 0);
    load_stage(1, BK);

#pragma unroll
    for (int kc = 0; kc < KC; kc++) {
        wait_groups(kc >= KC - 1 ? 0 : 1);
        __syncthreads();
        if (kc + 2 < KC) load_stage((kc + 2) % RING, (kc + 2) * BK);

        uint32_t sa = smem_base + (kc % RING) * STAGE;
        uint32_t sb = sa + ABYTES;
#pragma unroll
        for (int kb2 = 0; kb2 < 2; kb2++) {
            uint32_t br[2][4];
#pragma unroll
            for (int j = 0; j < 2; j++) {
                int r = b_r[j];
                uint32_t addr = sb + (uint32_t)(((r << 3) + ((kb2 * 4 + b_klo) ^ (r & 7))) * 16);
                ldsm_x4(addr, br[j][0], br[j][1], br[j][2], br[j][3]);
            }
#pragma unroll
            for (int ks2 = 0; ks2 < 2; ks2++) {
                uint32_t ar[4];
                {
                    int r = a_r;
                    uint32_t addr = sa + (uint32_t)(((r << 3) +
                        ((kb2 * 4 + ks2 * 2 + a_klo) ^ (r & 7))) * 16);
                    ldsm_x4(addr, ar[0], ar[1], ar[2], ar[3]);
                }
#pragma unroll
                for (int j = 0; j < 2; j++)
                    mma_bf16(acc[j], ar, br[j][2 * ks2], br[j][2 * ks2 + 1]);
            }
        }
    }

#pragma unroll
    for (int j = 0; j < 2; j++) {
        int row = m0 + (lane >> 2);
        int col = 8 * j + (lane & 3) * 2;
#pragma unroll
        for (int half = 0; half < 2; half++) {
            size_t off = (bm + row + 8 * half) * (size_t)NPP + col;
            *(float2*)(g_pr + off) = make_float2(acc[j][2 * half], acc[j][2 * half + 1]);
        }
    }
}

// ====== depthwise causal conv k=3 + SiLU, vectorized 8 channels/thread ======
// 384 threads/block: 8 tokens x 48 channel-groups. Weights staged in SMEM.
__global__ __launch_bounds__(384)
void conv_silu_kernel(const float* __restrict__ cw, const float* __restrict__ cb)
{
    __shared__ float scw[DI * 3];
    __shared__ float scb[DI];
    for (int j = threadIdx.x; j < DI * 3; j += 384) scw[j] = cw[j];
    for (int j = threadIdx.x; j < DI;     j += 384) scb[j] = cb[j];
    __syncthreads();

    int g = threadIdx.x % 48;              // channel group (8 ch)
    int tl = threadIdx.x / 48;             // token within block
    size_t t = (size_t)blockIdx.x * 8 + tl;
    int l = (int)(t % LSEQ);
    int c0 = g * 8;

    const __nv_bfloat16* base = g_xz + t * NXZ + c0;
    uint4 vc = *(const uint4*)(base);
    uint4 v1 = (l >= 1) ? *(const uint4*)(base - NXZ) : make_uint4(0,0,0,0);
    uint4 v2 = (l >= 2) ? *(const uint4*)(base - 2*NXZ) : make_uint4(0,0,0,0);
    const __nv_bfloat162* pc = (const __nv_bfloat162*)&vc;
    const __nv_bfloat162* p1 = (const __nv_bfloat162*)&v1;
    const __nv_bfloat162* p2 = (const __nv_bfloat162*)&v2;

    uint4 outv;
    __nv_bfloat162* po = (__nv_bfloat162*)&outv;
#pragma unroll
    for (int q = 0; q < 4; q++) {
        int i0 = c0 + 2 * q, i1 = i0 + 1;
        float a0 = scb[i0], a1 = scb[i1];
        float2 f2 = __bfloat1622float2(p2[q]);
        float2 f1 = __bfloat1622float2(p1[q]);
        float2 fc = __bfloat1622float2(pc[q]);
        a0 = fmaf(f2.x, scw[i0*3+0], a0);
        a1 = fmaf(f2.y, scw[i1*3+0], a1);
        a0 = fmaf(f1.x, scw[i0*3+1], a0);
        a1 = fmaf(f1.y, scw[i1*3+1], a1);
        a0 = fmaf(fc.x, scw[i0*3+2], a0);
        a1 = fmaf(fc.y, scw[i1*3+2], a1);
        po[q] = __floats2bfloat162_rn(siluf_(a0), siluf_(a1));
    }
    *(uint4*)(g_u + t * DI + c0) = outv;
}

// ========== dt + dA + dBu streaming kernel: block per token, 384 thr ==========
__global__ __launch_bounds__(384)
void dt_ad_kernel(const float* __restrict__ Wdt, const float* __restrict__ bdt,
                  const float* __restrict__ A_log)
{
    __shared__ float spr[NPP];
    size_t t = blockIdx.x;
    int i = threadIdx.x;
    if (i < NPP) spr[i] = g_pr[t * NPP + i];
    __syncthreads();

    float s = bdt[i];
#pragma unroll
    for (int k = 0; k < DTR; k++) s = fmaf(spr[k], Wdt[k * DI + i], s);
    float dt = softplusf_(s);
    float dA = expf(dt * (-expf(A_log[i])));
    float uu = __bfloat162float(g_u[t * DI + i]);
    float dbu = dt * spr[DTR] * uu;
    __nv_bfloat162 p;
    p.x = __float2bfloat16_rn(dA);
    p.y = __float2bfloat16_rn(dbu);
    g_ad[t * DI + i] = p;
    if (i == 0) g_Cv[t] = spr[DTR + 1];
}

// ================= chunked selective scan (pure FMA streaming) =================
__global__ void scan1_kernel()
{
    int idx = blockIdx.x * 256 + threadIdx.x;
    int i = idx % DI;
    int c = (idx / DI) % NC;
    int b = idx / (DI * NC);
    size_t t0 = (size_t)b * LSEQ + (size_t)c * CL;
    float h = 0.f, ap = 1.f;
#pragma unroll 4
    for (int s = 0; s < CL; s++) {
        __nv_bfloat162 p = g_ad[(t0 + s) * DI + i];
        float dA = __bfloat162float(p.x);
        h = fmaf(dA, h, __bfloat162float(p.y));
        ap *= dA;
    }
    g_ca[idx] = ap; g_ch[idx] = h;
}

__global__ void scan2_kernel()
{
    int idx = blockIdx.x * 256 + threadIdx.x;
    int i = idx % DI;
    int b = idx / DI;
    float h = 0.f;
    for (int c = 0; c < NC; c++) {
        int j = (b * NC + c) * DI + i;
        g_hi[j] = h;
        h = fmaf(g_ca[j], h, g_ch[j]);
    }
}

__global__ void scan3_kernel(const float* __restrict__ Dw)
{
    int idx = blockIdx.x * 256 + threadIdx.x;
    int i = idx % DI;
    int c = (idx / DI) % NC;
    int b = idx / (DI * NC);
    float Dv = Dw[i];
    size_t t0 = (size_t)b * LSEQ + (size_t)c * CL;
    float h = g_hi[idx];
#pragma unroll 4
    for (int s = 0; s < CL; s++) {
        size_t t = t0 + s;
        __nv_bfloat162 p = g_ad[t * DI + i];
        h = fmaf(__bfloat162float(p.x), h, __bfloat162float(p.y));
        float uu = __bfloat162float(g_u[t * DI + i]);
        float y = fmaf(h, g_Cv[t], uu * Dv);
        float z = __bfloat162float(g_xz[t * NXZ + DI + i]);
        g_yp[t * DI + i] = __float2bfloat16_rn(y * siluf_(z));
    }
}

extern "C" void kernel_launch(void* const* d_in, const int* in_sizes, int n_in,
                              void* d_out, int out_size)
{
    const float* x      = (const float*)d_in[0];
    const float* ln_w   = (const float*)d_in[1];
    const float* ln_b   = (const float*)d_in[2];
    const float* W_in   = (const float*)d_in[3];
    const float* conv_w = (const float*)d_in[4];
    const float* conv_b = (const float*)d_in[5];
    const float* W_xprj = (const float*)d_in[6];
    const float* W_dt   = (const float*)d_in[7];
    const float* b_dt   = (const float*)d_in[8];
    const float* A_log  = (const float*)d_in[9];
    const float* Dw     = (const float*)d_in[10];
    const float* W_out  = (const float*)d_in[11];
    float* out = (float*)d_out;

    __nv_bfloat16 *p_xnb, *p_xz, *p_yp, *p_Wt, *p_WoT;
    cudaGetSymbolAddress((void**)&p_xnb, g_xnb);
    cudaGetSymbolAddress((void**)&p_xz,  g_xz);
    cudaGetSymbolAddress((void**)&p_yp,  g_yp);
    cudaGetSymbolAddress((void**)&p_Wt,  g_Wt);
    cudaGetSymbolAddress((void**)&p_WoT, g_WoT);

    const int SMEM  = 3 * (128 + 64) * 64 * 2;   // 73728
    const int SMEMP = 3 * (128 + 16) * 64 * 2;   // 55296
    cudaFuncSetAttribute(hmma_gemm<CDIM,false>,
                         cudaFuncAttributeMaxDynamicSharedMemorySize, SMEM);
    cudaFuncSetAttribute(hmma_gemm<DI,true>,
                         cudaFuncAttributeMaxDynamicSharedMemorySize, SMEM);
    cudaFuncSetAttribute(proj_gemm,
                         cudaFuncAttributeMaxDynamicSharedMemorySize, SMEMP);

    // 0. weight transposes -> bf16 K-major (merged)
    wtrans_kernel<<<(NXZ*CDIM + CDIM*DI + NPP*DI + 255)/256, 256>>>(W_in, W_out, W_xprj);

    // 1. LayerNorm -> bf16
    ln_kernel<<<NTOK/8, 256>>>(x, ln_w, ln_b);

    // 2. xz = xn @ W_in  (HMMA bf16): [NTOK,192] x [192,768] -> bf16
    {
        dim3 grid(NXZ/64, NTOK/128);
        hmma_gemm<CDIM,false><<<grid, 256, SMEM>>>(p_xnb, p_Wt, nullptr, nullptr, p_xz, NXZ);
    }

    // 3. u = silu(causal depthwise conv(xb)), vectorized
    conv_silu_kernel<<<NTOK/8, 384>>>(conv_w, conv_b);

    // 4. proj GEMM: g_pr = u @ WxPad (HMMA)
    proj_gemm<<<NTOK/128, 256, SMEMP>>>();

    // 5. dt + dA + dBu streaming
    dt_ad_kernel<<<NTOK, 384>>>(W_dt, b_dt, A_log);

    // 6-8. chunked selective scan
    scan1_kernel<<<(NB*NC*DI)/256, 256>>>();
    scan2_kernel<<<(NB*DI)/256, 256>>>();
    scan3_kernel<<<(NB*NC*DI)/256, 256>>>(Dw);

    // 9. out = yp @ W_out + x  (HMMA bf16): [NTOK,384] x [384,192] -> fp32 + resid
    {
        dim3 grid(CDIM/64, NTOK/128);
        hmma_gemm<DI,true><<<grid, 256, SMEM>>>(p_yp, p_WoT, x, out, nullptr, CDIM);
    }
}

// round 9
// speedup vs baseline: 3.0503x; 1.2583x over previous
#include <cuda_runtime.h>
#include <cuda_bf16.h>
#include <cstdint>
#include <cstddef>

// Problem constants
#define NB   16
#define LSEQ 9216
#define NTOK 147456          // NB*LSEQ
#define CDIM 192
#define DI   384             // d_inner
#define NXZ  768             // 2*DI
#define DTR  12              // dt_rank
#define NPROJ 14             // dt_rank + 2*d_state
#define NPP  16              // padded proj cols
#define NC   36              // scan chunks per sequence
#define CL   256             // chunk length (NC*CL = LSEQ)
#define TRUN 32              // conv tokens per thread

// -------- scratch (device globals; no allocation allowed) --------
__device__ __nv_bfloat16  g_xnb[(size_t)NTOK * CDIM];  // layernorm output (bf16)
__device__ __nv_bfloat16  g_xz [(size_t)NTOK * NXZ];   // cols [0,384)=xb, [384,768)=z
__device__ __nv_bfloat16  g_u  [(size_t)NTOK * DI];    // silu(conv(xb))
__device__ __nv_bfloat162 g_ad [(size_t)NTOK * DI];    // {dA, dBu} per (t,i)
__device__ __nv_bfloat16  g_yp [(size_t)NTOK * DI];    // gated scan output
__device__ float          g_pr [(size_t)NTOK * NPP];   // proj output (fp32)
__device__ __nv_bfloat16  g_Wt [NXZ * CDIM];           // W_in^T  [768,192] K-major
__device__ __nv_bfloat16  g_WoT[CDIM * DI];            // W_out^T [192,384] K-major
__device__ __nv_bfloat16  g_WxT[NPP * DI];             // W_xproj^T padded [16,384] K-major
__device__ float g_Cv[NTOK];
__device__ float g_ca[NB * NC * DI];
__device__ float g_ch[NB * NC * DI];
__device__ float g_hi[NB * NC * DI];

__device__ __forceinline__ float sigmoidf_(float v) { return 1.0f / (1.0f + expf(-v)); }
__device__ __forceinline__ float siluf_(float v)    { return v * sigmoidf_(v); }
__device__ __forceinline__ float softplusf_(float v){ return v > 20.0f ? v : log1pf(expf(v)); }

__device__ __forceinline__ uint32_t smem_u32(const void* p) {
    uint32_t a;
    asm("{ .reg .u64 t; cvta.to.shared.u64 t, %1; cvt.u32.u64 %0, t; }" : "=r"(a) : "l"(p));
    return a;
}
__device__ __forceinline__ void ldsm_x4(uint32_t addr, uint32_t& r0, uint32_t& r1,
                                        uint32_t& r2, uint32_t& r3) {
    asm volatile("ldmatrix.sync.aligned.m8n8.x4.shared.b16 {%0,%1,%2,%3}, [%4];"
                 : "=r"(r0), "=r"(r1), "=r"(r2), "=r"(r3) : "r"(addr));
}
__device__ __forceinline__ void mma_bf16(float* c, const uint32_t* a, uint32_t b0, uint32_t b1) {
    asm volatile("mma.sync.aligned.m16n8k16.row.col.f32.bf16.bf16.f32 "
                 "{%0,%1,%2,%3}, {%4,%5,%6,%7}, {%8,%9}, {%0,%1,%2,%3};"
                 : "+f"(c[0]), "+f"(c[1]), "+f"(c[2]), "+f"(c[3])
                 : "r"(a[0]), "r"(a[1]), "r"(a[2]), "r"(a[3]), "r"(b0), "r"(b1));
}
__device__ __forceinline__ void cp16(uint32_t s, const void* g) {
    asm volatile("cp.async.cg.shared.global [%0], [%1], 16;" :: "r"(s), "l"(g));
}
__device__ __forceinline__ void wait_groups(int n) {
    if (n == 0)      asm volatile("cp.async.wait_group 0;");
    else if (n == 1) asm volatile("cp.async.wait_group 1;");
}

// ================= weight transposes (tiny, merged) =================
__global__ void wtrans_kernel(const float* __restrict__ W_in,
                              const float* __restrict__ W_out,
                              const float* __restrict__ Wx) {
    int i = blockIdx.x * 256 + threadIdx.x;
    if (i < NXZ * CDIM) {
        int n = i / CDIM, k = i % CDIM;
        g_Wt[i] = __float2bfloat16_rn(W_in[(size_t)k * NXZ + n]);
    }
    int j = i - NXZ * CDIM;
    if (j >= 0 && j < CDIM * DI) {
        int n = j / DI, k = j % DI;
        g_WoT[j] = __float2bfloat16_rn(W_out[(size_t)k * CDIM + n]);
    }
    int q = j - CDIM * DI;
    if (q >= 0 && q < NPP * DI) {
        int n = q / DI, k = q % DI;
        g_WxT[q] = (n < NPROJ) ? __float2bfloat16_rn(Wx[(size_t)k * NPROJ + n])
                               : __float2bfloat16_rn(0.f);
    }
}

// ================= LayerNorm -> bf16 =================
__global__ void ln_kernel(const float* __restrict__ x,
                          const float* __restrict__ w,
                          const float* __restrict__ b)
{
    int warp = threadIdx.x >> 5, lane = threadIdx.x & 31;
    size_t t = (size_t)blockIdx.x * 8 + warp;
    const float* row = x + t * CDIM;
    float v[6];
    float s = 0.f;
#pragma unroll
    for (int r = 0; r < 6; r++) { v[r] = row[lane + 32*r]; s += v[r]; }
#pragma unroll
    for (int o = 16; o; o >>= 1) s += __shfl_xor_sync(0xffffffffu, s, o);
    float mu = s * (1.0f/192.0f);
    float q = 0.f;
#pragma unroll
    for (int r = 0; r < 6; r++) { float d = v[r] - mu; q += d*d; }
#pragma unroll
    for (int o = 16; o; o >>= 1) q += __shfl_xor_sync(0xffffffffu, q, o);
    float inv = rsqrtf(q * (1.0f/192.0f) + 1e-5f);
    __nv_bfloat16* out = g_xnb + t * CDIM;
#pragma unroll
    for (int r = 0; r < 6; r++) {
        int c = lane + 32*r;
        out[c] = __float2bfloat16_rn((v[r] - mu) * inv * w[c] + b[c]);
    }
}

// ================= pipelined HMMA bf16 GEMM (3-stage ring, 1 sync/iter) =====
template<int K, bool RESID>
__global__ __launch_bounds__(256, 3)
void hmma_gemm(const __nv_bfloat16* __restrict__ A,
               const __nv_bfloat16* __restrict__ Bw,
               const float* __restrict__ resid,
               float* __restrict__ outf,
               __nv_bfloat16* __restrict__ outb,
               int N)
{
    constexpr int BM = 128, BN = 64, BK = 64;
    constexpr int KC = K / BK;
    constexpr int RING = 3;
    constexpr int ABYTES = BM * BK * 2;
    constexpr int STAGE  = (BM + BN) * BK * 2;
    extern __shared__ char smem[];
    int tid = threadIdx.x, wid = tid >> 5, lane = tid & 31;
    size_t bm = (size_t)blockIdx.y * BM;
    int bn = blockIdx.x * BN;
    int m0 = (wid & 3) * 32, n0 = (wid >> 2) * 32;

    uint32_t smem_base = smem_u32(smem);

    int arow[4], ach[4];
#pragma unroll
    for (int it = 0; it < 4; it++) {
        int c = tid + it * 256;
        arow[it] = c >> 3; ach[it] = c & 7;
    }
    int brow[2], bch[2];
#pragma unroll
    for (int it = 0; it < 2; it++) {
        int c = tid + it * 256;
        brow[it] = c >> 3; bch[it] = c & 7;
    }

    auto load_stage = [&](int st, int k0) {
        uint32_t sbase = smem_base + st * STAGE;
#pragma unroll
        for (int it = 0; it < 4; it++) {
            int row = arow[it], ch = ach[it];
            cp16(sbase + (uint32_t)(((row << 3) + (ch ^ (row & 7))) * 16),
                 A + (bm + row) * K + k0 + ch * 8);
        }
#pragma unroll
        for (int it = 0; it < 2; it++) {
            int row = brow[it], ch = bch[it];
            cp16(sbase + ABYTES + (uint32_t)(((row << 3) + (ch ^ (row & 7))) * 16),
                 Bw + (size_t)(bn + row) * K + k0 + ch * 8);
        }
        asm volatile("cp.async.commit_group;");
    };

    float acc[2][4][4];
#pragma unroll
    for (int ti = 0; ti < 2; ti++)
#pragma unroll
        for (int j = 0; j < 4; j++)
#pragma unroll
            for (int e = 0; e < 4; e++) acc[ti][j][e] = 0.f;

    int a_r[2], b_r[4];
#pragma unroll
    for (int ti = 0; ti < 2; ti++) a_r[ti] = m0 + 16 * ti + (lane & 15);
#pragma unroll
    for (int j = 0; j < 4; j++)    b_r[j]  = n0 + 8 * j + (lane & 7);
    int a_klo = lane >> 4;
    int b_klo = lane >> 3;

    load_stage(0, 0);
    load_stage(1, BK);

#pragma unroll
    for (int kc = 0; kc < KC; kc++) {
        wait_groups(kc >= KC - 1 ? 0 : 1);
        __syncthreads();
        if (kc + 2 < KC) load_stage((kc + 2) % RING, (kc + 2) * BK);

        uint32_t sa = smem_base + (kc % RING) * STAGE;
        uint32_t sb = sa + ABYTES;
#pragma unroll
        for (int kb2 = 0; kb2 < 2; kb2++) {
            uint32_t br[4][4];
#pragma unroll
            for (int j = 0; j < 4; j++) {
                int r = b_r[j];
                uint32_t addr = sb + (uint32_t)(((r << 3) + ((kb2 * 4 + b_klo) ^ (r & 7))) * 16);
                ldsm_x4(addr, br[j][0], br[j][1], br[j][2], br[j][3]);
            }
#pragma unroll
            for (int ks2 = 0; ks2 < 2; ks2++) {
                uint32_t ar[2][4];
#pragma unroll
                for (int ti = 0; ti < 2; ti++) {
                    int r = a_r[ti];
                    uint32_t addr = sa + (uint32_t)(((r << 3) +
                        ((kb2 * 4 + ks2 * 2 + a_klo) ^ (r & 7))) * 16);
                    ldsm_x4(addr, ar[ti][0], ar[ti][1], ar[ti][2], ar[ti][3]);
                }
#pragma unroll
                for (int ti = 0; ti < 2; ti++)
#pragma unroll
                    for (int j = 0; j < 4; j++)
                        mma_bf16(acc[ti][j], ar[ti], br[j][2 * ks2], br[j][2 * ks2 + 1]);
            }
        }
    }

#pragma unroll
    for (int ti = 0; ti < 2; ti++)
#pragma unroll
        for (int j = 0; j < 4; j++) {
            int row = m0 + 16 * ti + (lane >> 2);
            int col = bn + n0 + 8 * j + (lane & 3) * 2;
#pragma unroll
            for (int half = 0; half < 2; half++) {
                size_t off = (bm + row + 8 * half) * (size_t)N + col;
                float v0 = acc[ti][j][2 * half], v1 = acc[ti][j][2 * half + 1];
                if (RESID) {
                    float2 rv = *(const float2*)(resid + off);
                    *(float2*)(outf + off) = make_float2(v0 + rv.x, v1 + rv.y);
                } else {
                    __nv_bfloat162 p;
                    p.x = __float2bfloat16_rn(v0);
                    p.y = __float2bfloat16_rn(v1);
                    *(__nv_bfloat162*)(outb + off) = p;
                }
            }
        }
}

// ============ proj GEMM: g_pr[NTOK,16] = u[NTOK,384] @ WxT^T ============
__global__ __launch_bounds__(256, 3)
void proj_gemm()
{
    constexpr int BM = 128, BK = 64, K = DI, KC = K / BK, RING = 3;
    constexpr int ABYTES = BM * BK * 2;
    constexpr int STAGE  = ABYTES + NPP * BK * 2;
    extern __shared__ char smem[];
    const __nv_bfloat16* A = g_u;
    int tid = threadIdx.x, wid = tid >> 5, lane = tid & 31;
    size_t bm = (size_t)blockIdx.x * BM;
    int m0 = wid * 16;

    uint32_t smem_base = smem_u32(smem);

    int arow[4], ach[4];
#pragma unroll
    for (int it = 0; it < 4; it++) {
        int c = tid + it * 256;
        arow[it] = c >> 3; ach[it] = c & 7;
    }
    int brow = tid >> 3, bch = tid & 7;

    auto load_stage = [&](int st, int k0) {
        uint32_t sbase = smem_base + st * STAGE;
#pragma unroll
        for (int it = 0; it < 4; it++) {
            int row = arow[it], ch = ach[it];
            cp16(sbase + (uint32_t)(((row << 3) + (ch ^ (row & 7))) * 16),
                 A + (bm + row) * K + k0 + ch * 8);
        }
        if (tid < NPP * 8) {
            cp16(sbase + ABYTES + (uint32_t)(((brow << 3) + (bch ^ (brow & 7))) * 16),
                 g_WxT + (size_t)brow * K + k0 + bch * 8);
        }
        asm volatile("cp.async.commit_group;");
    };

    float acc[2][4];
#pragma unroll
    for (int j = 0; j < 2; j++)
#pragma unroll
        for (int e = 0; e < 4; e++) acc[j][e] = 0.f;

    int a_r = m0 + (lane & 15);
    int b_r[2];
#pragma unroll
    for (int j = 0; j < 2; j++) b_r[j] = 8 * j + (lane & 7);
    int a_klo = lane >> 4;
    int b_klo = lane >> 3;

    load_stage(0, 0);
    load_stage(1, BK);

#pragma unroll
    for (int kc = 0; kc < KC; kc++) {
        wait_groups(kc >= KC - 1 ? 0 : 1);
        __syncthreads();
        if (kc + 2 < KC) load_stage((kc + 2) % RING, (kc + 2) * BK);

        uint32_t sa = smem_base + (kc % RING) * STAGE;
        uint32_t sb = sa + ABYTES;
#pragma unroll
        for (int kb2 = 0; kb2 < 2; kb2++) {
            uint32_t br[2][4];
#pragma unroll
            for (int j = 0; j < 2; j++) {
                int r = b_r[j];
                uint32_t addr = sb + (uint32_t)(((r << 3) + ((kb2 * 4 + b_klo) ^ (r & 7))) * 16);
                ldsm_x4(addr, br[j][0], br[j][1], br[j][2], br[j][3]);
            }
#pragma unroll
            for (int ks2 = 0; ks2 < 2; ks2++) {
                uint32_t ar[4];
                {
                    int r = a_r;
                    uint32_t addr = sa + (uint32_t)(((r << 3) +
                        ((kb2 * 4 + ks2 * 2 + a_klo) ^ (r & 7))) * 16);
                    ldsm_x4(addr, ar[0], ar[1], ar[2], ar[3]);
                }
#pragma unroll
                for (int j = 0; j < 2; j++)
                    mma_bf16(acc[j], ar, br[j][2 * ks2], br[j][2 * ks2 + 1]);
            }
        }
    }

#pragma unroll
    for (int j = 0; j < 2; j++) {
        int row = m0 + (lane >> 2);
        int col = 8 * j + (lane & 3) * 2;
#pragma unroll
        for (int half = 0; half < 2; half++) {
            size_t off = (bm + row + 8 * half) * (size_t)NPP + col;
            *(float2*)(g_pr + off) = make_float2(acc[j][2 * half], acc[j][2 * half + 1]);
        }
    }
}

// ====== conv k=3 + SiLU: rolling window, 8 ch x TRUN tokens per thread ======
__global__ __launch_bounds__(256)
void conv_silu_kernel(const float* __restrict__ cw, const float* __restrict__ cb)
{
    int gidx = blockIdx.x * 256 + threadIdx.x;   // over NB*(LSEQ/TRUN)*48
    int g = gidx % 48;
    int run = gidx / 48;
    int l0 = (run % (LSEQ / TRUN)) * TRUN;
    int b  = run / (LSEQ / TRUN);
    int c0 = g * 8;
    size_t t0 = (size_t)b * LSEQ + l0;

    float w0[8], w1[8], w2[8], bb[8];
#pragma unroll
    for (int q = 0; q < 8; q++) {
        w0[q] = cw[(c0 + q) * 3 + 0];
        w1[q] = cw[(c0 + q) * 3 + 1];
        w2[q] = cw[(c0 + q) * 3 + 2];
        bb[q] = cb[c0 + q];
    }

    const __nv_bfloat16* base = g_xz + t0 * NXZ + c0;
    float f1[8], f2[8];
#pragma unroll
    for (int q = 0; q < 8; q++) { f1[q] = 0.f; f2[q] = 0.f; }
    if (l0 >= 1) {
        uint4 v = *(const uint4*)(base - NXZ);
        const __nv_bfloat162* p = (const __nv_bfloat162*)&v;
#pragma unroll
        for (int q = 0; q < 4; q++) {
            float2 f = __bfloat1622float2(p[q]);
            f1[2*q] = f.x; f1[2*q+1] = f.y;
        }
    }
    if (l0 >= 2) {
        uint4 v = *(const uint4*)(base - 2 * NXZ);
        const __nv_bfloat162* p = (const __nv_bfloat162*)&v;
#pragma unroll
        for (int q = 0; q < 4; q++) {
            float2 f = __bfloat1622float2(p[q]);
            f2[2*q] = f.x; f2[2*q+1] = f.y;
        }
    }

#pragma unroll 4
    for (int s = 0; s < TRUN; s++) {
        uint4 v = *(const uint4*)(base + (size_t)s * NXZ);
        const __nv_bfloat162* p = (const __nv_bfloat162*)&v;
        float fc[8];
#pragma unroll
        for (int q = 0; q < 4; q++) {
            float2 f = __bfloat1622float2(p[q]);
            fc[2*q] = f.x; fc[2*q+1] = f.y;
        }
        uint4 outv;
        __nv_bfloat162* po = (__nv_bfloat162*)&outv;
#pragma unroll
        for (int q = 0; q < 4; q++) {
            float a0 = bb[2*q],   a1 = bb[2*q+1];
            a0 = fmaf(f2[2*q], w0[2*q], a0);     a1 = fmaf(f2[2*q+1], w0[2*q+1], a1);
            a0 = fmaf(f1[2*q], w1[2*q], a0);     a1 = fmaf(f1[2*q+1], w1[2*q+1], a1);
            a0 = fmaf(fc[2*q], w2[2*q], a0);     a1 = fmaf(fc[2*q+1], w2[2*q+1], a1);
            po[q] = __floats2bfloat162_rn(siluf_(a0), siluf_(a1));
        }
        *(uint4*)(g_u + (t0 + s) * DI + c0) = outv;
#pragma unroll
        for (int q = 0; q < 8; q++) { f2[q] = f1[q]; f1[q] = fc[q]; }
    }
}

// ==== fused dt + dA + dBu + chunk-scan pass1: block per (b,chunk), 384 thr ====
__global__ __launch_bounds__(384)
void dtscan1_kernel(const float* __restrict__ Wdt, const float* __restrict__ bdt,
                    const float* __restrict__ A_log)
{
    __shared__ float spr[CL * NPP];     // 16 KB: pr tile for this chunk
    int bc = blockIdx.x;                // b*NC + c
    int i = threadIdx.x;
    int b = bc / NC, c = bc % NC;
    size_t t0 = (size_t)b * LSEQ + (size_t)c * CL;

    // stage pr tile (and emit g_Cv)
    for (int idx = i; idx < CL * NPP; idx += 384) {
        float v = g_pr[t0 * NPP + idx];
        spr[idx] = v;
        if ((idx & 15) == 13) g_Cv[t0 + (idx >> 4)] = v;
    }

    float wr[DTR];
#pragma unroll
    for (int k = 0; k < DTR; k++) wr[k] = Wdt[k * DI + i];
    float bias = bdt[i];
    float Ai = -expf(A_log[i]);
    __syncthreads();

    float h = 0.f, ap = 1.f;
#pragma unroll 4
    for (int s = 0; s < CL; s++) {
        const float* pp = &spr[s * NPP];
        float sd = bias;
#pragma unroll
        for (int k = 0; k < DTR; k++) sd = fmaf(pp[k], wr[k], sd);
        float dt = softplusf_(sd);
        float dA = expf(dt * Ai);
        float uu = __bfloat162float(g_u[(t0 + s) * DI + i]);
        float dbu = dt * pp[DTR] * uu;
        __nv_bfloat162 p;
        p.x = __float2bfloat16_rn(dA);
        p.y = __float2bfloat16_rn(dbu);
        g_ad[(t0 + s) * DI + i] = p;
        h = fmaf(__bfloat162float(p.x), h, __bfloat162float(p.y));
        ap *= __bfloat162float(p.x);
    }
    g_ca[bc * DI + i] = ap;
    g_ch[bc * DI + i] = h;
}

// ================= scan pass 2 + 3 =================
__global__ void scan2_kernel()
{
    int idx = blockIdx.x * 256 + threadIdx.x;   // b*DI + i
    int i = idx % DI;
    int b = idx / DI;
    float h = 0.f;
    for (int c = 0; c < NC; c++) {
        int j = (b * NC + c) * DI + i;
        g_hi[j] = h;
        h = fmaf(g_ca[j], h, g_ch[j]);
    }
}

__global__ void scan3_kernel(const float* __restrict__ Dw)
{
    int idx = blockIdx.x * 256 + threadIdx.x;
    int i = idx % DI;
    int c = (idx / DI) % NC;
    int b = idx / (DI * NC);
    float Dv = Dw[i];
    size_t t0 = (size_t)b * LSEQ + (size_t)c * CL;
    float h = g_hi[idx];
#pragma unroll 4
    for (int s = 0; s < CL; s++) {
        size_t t = t0 + s;
        __nv_bfloat162 p = g_ad[t * DI + i];
        h = fmaf(__bfloat162float(p.x), h, __bfloat162float(p.y));
        float uu = __bfloat162float(g_u[t * DI + i]);
        float y = fmaf(h, g_Cv[t], uu * Dv);
        float z = __bfloat162float(g_xz[t * NXZ + DI + i]);
        g_yp[t * DI + i] = __float2bfloat16_rn(y * siluf_(z));
    }
}

extern "C" void kernel_launch(void* const* d_in, const int* in_sizes, int n_in,
                              void* d_out, int out_size)
{
    const float* x      = (const float*)d_in[0];
    const float* ln_w   = (const float*)d_in[1];
    const float* ln_b   = (const float*)d_in[2];
    const float* W_in   = (const float*)d_in[3];
    const float* conv_w = (const float*)d_in[4];
    const float* conv_b = (const float*)d_in[5];
    const float* W_xprj = (const float*)d_in[6];
    const float* W_dt   = (const float*)d_in[7];
    const float* b_dt   = (const float*)d_in[8];
    const float* A_log  = (const float*)d_in[9];
    const float* Dw     = (const float*)d_in[10];
    const float* W_out  = (const float*)d_in[11];
    float* out = (float*)d_out;

    __nv_bfloat16 *p_xnb, *p_xz, *p_yp, *p_Wt, *p_WoT;
    cudaGetSymbolAddress((void**)&p_xnb, g_xnb);
    cudaGetSymbolAddress((void**)&p_xz,  g_xz);
    cudaGetSymbolAddress((void**)&p_yp,  g_yp);
    cudaGetSymbolAddress((void**)&p_Wt,  g_Wt);
    cudaGetSymbolAddress((void**)&p_WoT, g_WoT);

    const int SMEM  = 3 * (128 + 64) * 64 * 2;   // 73728
    const int SMEMP = 3 * (128 + 16) * 64 * 2;   // 55296
    cudaFuncSetAttribute(hmma_gemm<CDIM,false>,
                         cudaFuncAttributeMaxDynamicSharedMemorySize, SMEM);
    cudaFuncSetAttribute(hmma_gemm<DI,true>,
                         cudaFuncAttributeMaxDynamicSharedMemorySize, SMEM);
    cudaFuncSetAttribute(proj_gemm,
                         cudaFuncAttributeMaxDynamicSharedMemorySize, SMEMP);

    // 0. weight transposes -> bf16 K-major (merged)
    wtrans_kernel<<<(NXZ*CDIM + CDIM*DI + NPP*DI + 255)/256, 256>>>(W_in, W_out, W_xprj);

    // 1. LayerNorm -> bf16
    ln_kernel<<<NTOK/8, 256>>>(x, ln_w, ln_b);

    // 2. xz = xn @ W_in  (HMMA bf16): [NTOK,192] x [192,768] -> bf16
    {
        dim3 grid(NXZ/64, NTOK/128);
        hmma_gemm<CDIM,false><<<grid, 256, SMEM>>>(p_xnb, p_Wt, nullptr, nullptr, p_xz, NXZ);
    }

    // 3. u = silu(causal depthwise conv(xb)), rolling window
    conv_silu_kernel<<<(NB*(LSEQ/TRUN)*48)/256, 256>>>(conv_w, conv_b);

    // 4. proj GEMM: g_pr = u @ WxPad (HMMA)
    proj_gemm<<<NTOK/128, 256, SMEMP>>>();

    // 5. fused dt + dA + dBu + scan pass1
    dtscan1_kernel<<<NB*NC, 384>>>(W_dt, b_dt, A_log);

    // 6-7. scan pass2 + pass3
    scan2_kernel<<<(NB*DI)/256, 256>>>();
    scan3_kernel<<<(NB*NC*DI)/256, 256>>>(Dw);

    // 8. out = yp @ W_out + x  (HMMA bf16): [NTOK,384] x [384,192] -> fp32 + resid
    {
        dim3 grid(CDIM/64, NTOK/128);
        hmma_gemm<DI,true><<<grid, 256, SMEM>>>(p_yp, p_WoT, x, out, nullptr, CDIM);
    }
}